// round 5
// baseline (speedup 1.0000x reference)
#include <cuda_runtime.h>
#include <cuda_bf16.h>
#include <math.h>
#include <stdint.h>

#define NT 4000
#define NS 5000

// ===================== scratch (device globals) =============================
__device__ __align__(16) unsigned short g_A0h[16000000], g_A0l[16000000];
__device__ __align__(16) unsigned short g_A1h[20000000], g_A1l[20000000];
__device__ __align__(16) unsigned short g_A2h[25000000], g_A2l[25000000];
__device__ __align__(16) unsigned short g_Esh[25000000], g_Esl[25000000];
__device__ __align__(16) unsigned short g_Evh[20000000], g_Evl[20000000];
__device__ __align__(16) unsigned short g_Eth[16000000], g_Etl[16000000];
__device__ __align__(16) unsigned short g_Xth[128 * NS], g_Xtl[128 * NS];
__device__ float g_src_inv[NS];
__device__ float g_vna_inv[NT];
__device__ float g_tgt_inv[NT];
__device__ __align__(16) float g_lr[3 * NS * 128];
__device__ __align__(16) float g_semb[3 * NT * 128];
__device__ __align__(16) float g_Y[2 * NS * 128];
__device__ __align__(16) float g_T[NT * 128];
__device__ __align__(16) float g_xt[NT * 128];

// ===================== PTX helpers (sm_80+ only; NO tcgen05) ================
__device__ __forceinline__ uint32_t smem_u32(const void* p) {
    uint32_t a;
    asm("{ .reg .u64 t; cvta.to.shared.u64 t, %1; cvt.u32.u64 %0, t; }" : "=r"(a) : "l"(p));
    return a;
}

#define CP_ASYNC16(saddr, gaddr, sz) \
    asm volatile("cp.async.ca.shared.global [%0], [%1], 16, %2;" \
        :: "r"(saddr), "l"(gaddr), "r"(sz))
#define CP_COMMIT() asm volatile("cp.async.commit_group;" ::: "memory")
#define CP_WAIT1()  asm volatile("cp.async.wait_group 1;" ::: "memory")

#define LDSM4(r, a) \
    asm volatile("ldmatrix.sync.aligned.m8n8.x4.shared.b16 {%0,%1,%2,%3}, [%4];" \
        : "=r"((r)[0]), "=r"((r)[1]), "=r"((r)[2]), "=r"((r)[3]) : "r"(a))

#define MMA_BF16(c, A, b0, b1) \
    asm volatile("mma.sync.aligned.m16n8k16.row.col.f32.bf16.bf16.f32 " \
        "{%0,%1,%2,%3},{%4,%5,%6,%7},{%8,%9},{%0,%1,%2,%3};" \
        : "+f"((c)[0]), "+f"((c)[1]), "+f"((c)[2]), "+f"((c)[3]) \
        : "r"((A)[0]), "r"((A)[1]), "r"((A)[2]), "r"((A)[3]), "r"(b0), "r"(b1))

// ===================== pack / unpack ========================================
__global__ void pack_kernel(const float* __restrict__ x, float* __restrict__ xp, int n) {
    int i = blockIdx.x * blockDim.x + threadIdx.x;
    if (i >= n * 128) return;
    int r = i >> 7, c = i & 127, b = c >> 6, d = c & 63;
    xp[i] = x[((size_t)b * n + r) * 64 + d];
}
__global__ void unpack_kernel(const float* __restrict__ xp, float* __restrict__ out, int n) {
    int i = blockIdx.x * blockDim.x + threadIdx.x;
    if (i >= n * 128) return;
    int r = i >> 7, c = i & 127, b = c >> 6, d = c & 63;
    out[((size_t)b * n + r) * 64 + d] = xp[i];
}

// ===================== fp32 -> bf16 hi/lo split =============================
__global__ void split_kernel(const float* __restrict__ A,
                             unsigned short* __restrict__ H,
                             unsigned short* __restrict__ L, int n4) {
    int i = blockIdx.x * blockDim.x + threadIdx.x;
    if (i >= n4) return;
    float4 v = ((const float4*)A)[i];
    __nv_bfloat16 h0 = __float2bfloat16(v.x), h1 = __float2bfloat16(v.y);
    __nv_bfloat16 h2 = __float2bfloat16(v.z), h3 = __float2bfloat16(v.w);
    __nv_bfloat16 l0 = __float2bfloat16(v.x - __bfloat162float(h0));
    __nv_bfloat16 l1 = __float2bfloat16(v.y - __bfloat162float(h1));
    __nv_bfloat16 l2 = __float2bfloat16(v.z - __bfloat162float(h2));
    __nv_bfloat16 l3 = __float2bfloat16(v.w - __bfloat162float(h3));
    ushort4 hv, lv;
    hv.x = __bfloat16_as_ushort(h0); hv.y = __bfloat16_as_ushort(h1);
    hv.z = __bfloat16_as_ushort(h2); hv.w = __bfloat16_as_ushort(h3);
    lv.x = __bfloat16_as_ushort(l0); lv.y = __bfloat16_as_ushort(l1);
    lv.z = __bfloat16_as_ushort(l2); lv.w = __bfloat16_as_ushort(l3);
    ((ushort4*)H)[i] = hv;
    ((ushort4*)L)[i] = lv;
}

// ===================== adaptive adjacency (bf16 hi/lo out) ==================
__global__ __launch_bounds__(256)
void adp_kernel(const float* __restrict__ nv1, const float* __restrict__ nv2,
                unsigned short* __restrict__ Eh, unsigned short* __restrict__ El,
                float* __restrict__ inv, int nrows, int ncols)
{
    __shared__ float v1s[8][30];
    __shared__ float part[8][8];
    const int tid = threadIdx.x;
    const int r0 = blockIdx.x * 8;
    if (tid < 240) v1s[tid / 30][tid % 30] = nv1[(size_t)(r0 + tid / 30) * 30 + tid % 30];
    __syncthreads();

    float psum[8];
#pragma unroll
    for (int r = 0; r < 8; r++) psum[r] = 0.f;

    for (int c = tid; c < ncols; c += 256) {
        float col[30];
#pragma unroll
        for (int q = 0; q < 30; q++) col[q] = nv2[(size_t)q * ncols + c];
#pragma unroll
        for (int r = 0; r < 8; r++) {
            float dot = 0.f;
#pragma unroll
            for (int q = 0; q < 30; q++) dot = fmaf(v1s[r][q], col[q], dot);
            float t = fmaxf(dot, 0.f) * 1.4426950408889634f;
            float e;
            asm("ex2.approx.f32 %0, %1;" : "=f"(e) : "f"(t));
            __nv_bfloat16 h = __float2bfloat16(e);
            size_t idx = (size_t)(r0 + r) * ncols + c;
            Eh[idx] = __bfloat16_as_ushort(h);
            El[idx] = __bfloat16_as_ushort(__float2bfloat16(e - __bfloat162float(h)));
            psum[r] += e;
        }
    }
    const int lane = tid & 31, wid = tid >> 5;
#pragma unroll
    for (int r = 0; r < 8; r++) {
        float v = psum[r];
#pragma unroll
        for (int off = 16; off > 0; off >>= 1) v += __shfl_down_sync(0xffffffffu, v, off);
        if (lane == 0) part[wid][r] = v;
    }
    __syncthreads();
    if (tid < 8) {
        float s = 0.f;
#pragma unroll
        for (int w = 0; w < 8; w++) s += part[w][tid];
        inv[r0 + tid] = 1.0f / s;
    }
}

// ===================== X^T prep: [m,128] fp32 -> [128,m] bf16 hi/lo =========
__global__ __launch_bounds__(256)
void xt_prep(const float* __restrict__ X, unsigned short* __restrict__ Xh,
             unsigned short* __restrict__ Xl, int m)
{
    __shared__ float t[32][33];
    const int mb = blockIdx.x * 32, cb = blockIdx.y * 32;
    const int lx = threadIdx.x & 31, ly = threadIdx.x >> 5;
#pragma unroll
    for (int yy = ly; yy < 32; yy += 8) {
        int gm = mb + yy;
        t[yy][lx] = (gm < m) ? X[(size_t)gm * 128 + cb + lx] : 0.f;
    }
    __syncthreads();
#pragma unroll
    for (int yy = ly; yy < 32; yy += 8) {
        int c = cb + yy, gm = mb + lx;
        if (gm < m) {
            float v = t[lx][yy];
            __nv_bfloat16 h = __float2bfloat16(v);
            Xh[(size_t)c * m + gm] = __bfloat16_as_ushort(h);
            Xl[(size_t)c * m + gm] = __bfloat16_as_ushort(__float2bfloat16(v - __bfloat162float(h)));
        }
    }
}

// ===================== HMMA GEMM ============================================
// Y[z][n,128] = A_z[n,m] @ X[m,128]; fp32-accurate via bf16 hi/lo 3-pass.
// z==1 applies invsum row scale (softmax normalization folded).
// Block: 64(M) x 128(N), KT=64, 8 warps (2m x 4n), warp tile 32x32.
#define BM 64
#define GKT 64
#define STAGE_B 49152   // Ah 8K | Al 8K | Bh 16K | Bl 16K
#define SMEM_GEMM (2 * STAGE_B)

__device__ __forceinline__ void stage_load(
    uint32_t sdst, const unsigned short* __restrict__ Ah,
    const unsigned short* __restrict__ Al,
    const unsigned short* __restrict__ Xh, const unsigned short* __restrict__ Xl,
    int row0, int kbase, int n, int m, int tid)
{
    // A hi/lo: 64 rows x 64 k (8 x 16B chunks per row)
#pragma unroll
    for (int t = 0; t < 2; t++) {
        int id = tid + t * 256;
        int r = id >> 3, kc = id & 7;
        int gr = row0 + r, gk = kbase + kc * 8;
        bool v = (gr < n) && (gk < m);
        size_t gi = (size_t)(v ? gr : 0) * m + (v ? gk : 0);
        uint32_t off = r * 128 + kc * 16;
        uint32_t sw = off ^ ((off >> 3) & 0x70);
        unsigned sz = v ? 16u : 0u;
        CP_ASYNC16(sdst + sw, Ah + gi, sz);
        CP_ASYNC16(sdst + 8192 + sw, Al + gi, sz);
    }
    // B hi/lo: 128 rows (n-cols) x 64 k
#pragma unroll
    for (int t = 0; t < 4; t++) {
        int id = tid + t * 256;
        int r = id >> 3, kc = id & 7;
        int gk = kbase + kc * 8;
        bool v = (gk < m);
        size_t gi = (size_t)r * m + (v ? gk : 0);
        uint32_t off = r * 128 + kc * 16;
        uint32_t sw = off ^ ((off >> 3) & 0x70);
        unsigned sz = v ? 16u : 0u;
        CP_ASYNC16(sdst + 16384 + sw, Xh + gi, sz);
        CP_ASYNC16(sdst + 32768 + sw, Xl + gi, sz);
    }
}

__global__ __launch_bounds__(256, 2)
void hmma_gemm(const unsigned short* __restrict__ A0h, const unsigned short* __restrict__ A0l,
               const unsigned short* __restrict__ E1h, const unsigned short* __restrict__ E1l,
               const float* __restrict__ invsum,
               const unsigned short* __restrict__ Xh, const unsigned short* __restrict__ Xl,
               float* __restrict__ Y, int n, int m)
{
    extern __shared__ __align__(128) char smem[];
    const uint32_t sb = smem_u32(smem);
    const int tid = threadIdx.x, lane = tid & 31, wid = tid >> 5;
    const int wm = wid >> 2, wn = wid & 3;
    const unsigned short* __restrict__ Ah = blockIdx.z ? E1h : A0h;
    const unsigned short* __restrict__ Al = blockIdx.z ? E1l : A0l;
    const int row0 = blockIdx.x * BM;
    const int ktn = (m + GKT - 1) / GKT;

    float acc[2][4][4];
#pragma unroll
    for (int i = 0; i < 2; i++)
#pragma unroll
        for (int j = 0; j < 4; j++)
#pragma unroll
            for (int q = 0; q < 4; q++) acc[i][j][q] = 0.f;

    // ldmatrix lane addressing (row offset + xor term independent of k chunk)
    uint32_t arow[2], axor[2];
#pragma unroll
    for (int mt = 0; mt < 2; mt++) {
        int r = wm * 32 + mt * 16 + (lane & 7) + (((lane >> 3) & 1) << 3);
        arow[mt] = (uint32_t)r * 128;
        axor[mt] = ((uint32_t)r * 16) & 0x70;
    }
    const uint32_t akbs = ((lane >> 4) & 1) * 16;
    uint32_t brow[2], bxor[2];
#pragma unroll
    for (int bt = 0; bt < 2; bt++) {
        int r = wn * 32 + bt * 16 + (lane & 7) + (((lane >> 4) & 1) << 3);
        brow[bt] = (uint32_t)r * 128;
        bxor[bt] = ((uint32_t)r * 16) & 0x70;
    }
    const uint32_t bkbs = ((lane >> 3) & 1) * 16;

    // prologue
    stage_load(sb, Ah, Al, Xh, Xl, row0, 0, n, m, tid);
    CP_COMMIT();

    for (int kt = 0; kt < ktn; kt++) {
        if (kt + 1 < ktn)
            stage_load(sb + ((kt + 1) & 1) * STAGE_B, Ah, Al, Xh, Xl,
                       row0, (kt + 1) * GKT, n, m, tid);
        CP_COMMIT();
        CP_WAIT1();
        __syncthreads();

        const uint32_t stb = sb + (kt & 1) * STAGE_B;
#pragma unroll
        for (int ks = 0; ks < 4; ks++) {
            const uint32_t kb = ks * 32;
            uint32_t fah[2][4], fal[2][4], fbh[2][4], fbl[2][4];
#pragma unroll
            for (int mt = 0; mt < 2; mt++) {
                uint32_t ad = stb + arow[mt] + ((kb + akbs) ^ axor[mt]);
                LDSM4(fah[mt], ad);
                LDSM4(fal[mt], ad + 8192);
            }
#pragma unroll
            for (int bt = 0; bt < 2; bt++) {
                uint32_t bd = stb + 16384 + brow[bt] + ((kb + bkbs) ^ bxor[bt]);
                LDSM4(fbh[bt], bd);
                LDSM4(fbl[bt], bd + 16384);
            }
#pragma unroll
            for (int mt = 0; mt < 2; mt++) {
#pragma unroll
                for (int nt = 0; nt < 4; nt++) {
                    const int g = nt >> 1, h = (nt & 1) << 1;
                    MMA_BF16(acc[mt][nt], fah[mt], fbh[g][h], fbh[g][h + 1]);
                    MMA_BF16(acc[mt][nt], fah[mt], fbl[g][h], fbl[g][h + 1]);
                    MMA_BF16(acc[mt][nt], fal[mt], fbh[g][h], fbh[g][h + 1]);
                }
            }
        }
        __syncthreads();
    }

    // ---- store ----
    float* __restrict__ Yz = Y + (size_t)blockIdx.z * n * 128;
#pragma unroll
    for (int mt = 0; mt < 2; mt++) {
        int gr0 = row0 + wm * 32 + mt * 16 + (lane >> 2);
        int gr1 = gr0 + 8;
        float s0 = 1.f, s1 = 1.f;
        if (blockIdx.z) {
            if (gr0 < n) s0 = invsum[gr0];
            if (gr1 < n) s1 = invsum[gr1];
        }
#pragma unroll
        for (int nt = 0; nt < 4; nt++) {
            int col = wn * 32 + nt * 8 + ((lane & 3) << 1);
            if (gr0 < n) {
                float2 o = make_float2(acc[mt][nt][0] * s0, acc[mt][nt][1] * s0);
                *(float2*)(Yz + (size_t)gr0 * 128 + col) = o;
            }
            if (gr1 < n) {
                float2 o = make_float2(acc[mt][nt][2] * s1, acc[mt][nt][3] * s1);
                *(float2*)(Yz + (size_t)gr1 * 128 + col) = o;
            }
        }
    }
}

// ===================== GC epilogue ==========================================
__global__ __launch_bounds__(256)
void gc_epilogue_kernel(const float* __restrict__ Y, const float* __restrict__ W,
                        const float* __restrict__ bias, const float* __restrict__ prev,
                        float* __restrict__ out, int n)
{
    __shared__ float Ws[128][64];
    __shared__ float Y1s[8][128];
    __shared__ float Y2s[8][128];
    const int tid = threadIdx.x;
    const int r0 = blockIdx.x * 8;
    for (int i = tid; i < 128 * 64; i += 256) Ws[i >> 6][i & 63] = W[i];
    const float* __restrict__ Y2 = Y + (size_t)n * 128;
    for (int i = tid; i < 8 * 128; i += 256) {
        int r = i >> 7, c = i & 127;
        int gr = r0 + r;
        float v1 = 0.f, v2 = 0.f;
        if (gr < n) { v1 = Y[(size_t)gr * 128 + c]; v2 = Y2[(size_t)gr * 128 + c]; }
        Y1s[r][c] = v1; Y2s[r][c] = v2;
    }
    __syncthreads();
    const int c = tid & 127, rg = tid >> 7, d = c & 63, b64 = c & 64;
    const float bv = bias[d];
    for (int rr = rg; rr < 8; rr += 2) {
        int gr = r0 + rr;
        if (gr >= n) break;
        float acc = bv;
#pragma unroll
        for (int k = 0; k < 64; k++) {
            acc = fmaf(Y1s[rr][b64 + k], Ws[k][d], acc);
            acc = fmaf(Y2s[rr][b64 + k], Ws[64 + k][d], acc);
        }
        float g = fmaxf(acc, 0.f);
        out[(size_t)gr * 128 + c] = prev ? (prev[(size_t)gr * 128 + c] + g) : g;
    }
}

// ===================== gated fusion =========================================
__global__ __launch_bounds__(256)
void fusion_kernel(const float* __restrict__ T, const float* __restrict__ S,
                   const float* __restrict__ Wt, const float* __restrict__ Wsrc,
                   const float* __restrict__ fb, float* __restrict__ xt, int n)
{
    __shared__ float Wts[64][64];
    __shared__ float Wss[64][64];
    __shared__ float Ts[8][128];
    __shared__ float Ss[8][128];
    const int tid = threadIdx.x;
    const int r0 = blockIdx.x * 8;
    for (int i = tid; i < 64 * 64; i += 256) { Wts[i >> 6][i & 63] = Wt[i]; Wss[i >> 6][i & 63] = Wsrc[i]; }
    for (int i = tid; i < 8 * 128; i += 256) {
        int r = i >> 7, c = i & 127;
        int gr = r0 + r;
        float tv = 0.f, sv = 0.f;
        if (gr < n) { tv = T[(size_t)gr * 128 + c]; sv = S[(size_t)gr * 128 + c]; }
        Ts[r][c] = tv; Ss[r][c] = sv;
    }
    __syncthreads();
    const int c = tid & 127, rg = tid >> 7, d = c & 63, b64 = c & 64;
    const float bv = fb[d];
    for (int rr = rg; rr < 8; rr += 2) {
        int gr = r0 + rr;
        if (gr >= n) break;
        float acc = bv;
#pragma unroll
        for (int k = 0; k < 64; k++) {
            acc = fmaf(Ts[rr][b64 + k], Wts[k][d], acc);
            acc = fmaf(Ss[rr][b64 + k], Wss[k][d], acc);
        }
        float z = 1.f / (1.f + expf(-acc));
        xt[(size_t)gr * 128 + c] += z * Ts[rr][c] + (1.f - z) * Ss[rr][c];
    }
}

// ===================== launcher =============================================
extern "C" void kernel_launch(void* const* d_in, const int* in_sizes, int n_in,
                              void* d_out, int out_size)
{
    (void)in_sizes; (void)n_in; (void)out_size;
    const float* A0      = (const float*)d_in[0];
    const float* A1      = (const float*)d_in[1];
    const float* A2      = (const float*)d_in[2];
    const float* x0      = (const float*)d_in[3];
    const float* x1      = (const float*)d_in[4];
    const float* src_nv1 = (const float*)d_in[5];
    const float* src_nv2 = (const float*)d_in[6];
    const float* src_W   = (const float*)d_in[7];
    const float* src_b   = (const float*)d_in[8];
    const float* vna_nv1 = (const float*)d_in[9];
    const float* vna_nv2 = (const float*)d_in[10];
    const float* vna_W   = (const float*)d_in[11];
    const float* vna_b   = (const float*)d_in[12];
    const float* tgt_nv1 = (const float*)d_in[13];
    const float* tgt_nv2 = (const float*)d_in[14];
    const float* tgt_W   = (const float*)d_in[15];
    const float* tgt_b   = (const float*)d_in[16];
    const float* fus_Wt  = (const float*)d_in[17];
    const float* fus_Ws  = (const float*)d_in[18];
    const float* fus_b   = (const float*)d_in[19];

    unsigned short *A0h, *A0l, *A1h, *A1l, *A2h, *A2l;
    unsigned short *Esh, *Esl, *Evh, *Evl, *Eth, *Etl, *Xth, *Xtl;
    float *src_inv, *vna_inv, *tgt_inv, *lr, *semb, *Yb, *Tb, *xtb;
    cudaGetSymbolAddress((void**)&A0h, g_A0h); cudaGetSymbolAddress((void**)&A0l, g_A0l);
    cudaGetSymbolAddress((void**)&A1h, g_A1h); cudaGetSymbolAddress((void**)&A1l, g_A1l);
    cudaGetSymbolAddress((void**)&A2h, g_A2h); cudaGetSymbolAddress((void**)&A2l, g_A2l);
    cudaGetSymbolAddress((void**)&Esh, g_Esh); cudaGetSymbolAddress((void**)&Esl, g_Esl);
    cudaGetSymbolAddress((void**)&Evh, g_Evh); cudaGetSymbolAddress((void**)&Evl, g_Evl);
    cudaGetSymbolAddress((void**)&Eth, g_Eth); cudaGetSymbolAddress((void**)&Etl, g_Etl);
    cudaGetSymbolAddress((void**)&Xth, g_Xth); cudaGetSymbolAddress((void**)&Xtl, g_Xtl);
    cudaGetSymbolAddress((void**)&src_inv, g_src_inv);
    cudaGetSymbolAddress((void**)&vna_inv, g_vna_inv);
    cudaGetSymbolAddress((void**)&tgt_inv, g_tgt_inv);
    cudaGetSymbolAddress((void**)&lr,   g_lr);
    cudaGetSymbolAddress((void**)&semb, g_semb);
    cudaGetSymbolAddress((void**)&Yb,   g_Y);
    cudaGetSymbolAddress((void**)&Tb,   g_T);
    cudaGetSymbolAddress((void**)&xtb,  g_xt);

    cudaFuncSetAttribute(hmma_gemm, cudaFuncAttributeMaxDynamicSharedMemorySize, SMEM_GEMM);

    // pack inputs into [n,128] (col = b*64+d)
    pack_kernel<<<(NS * 128 + 255) / 256, 256>>>(x1, lr, NS);
    pack_kernel<<<(NT * 128 + 255) / 256, 256>>>(x0, xtb, NT);

    // dense adjacency hi/lo splits
    split_kernel<<<(NT * NT / 4 + 255) / 256, 256>>>(A0, A0h, A0l, NT * NT / 4);
    split_kernel<<<(NT * NS / 4 + 255) / 256, 256>>>(A1, A1h, A1l, NT * NS / 4);
    split_kernel<<<(NS * NS / 4 + 255) / 256, 256>>>(A2, A2h, A2l, NS * NS / 4);

    // adaptive adjacencies (unnormalized exp hi/lo + inverse row sums)
    adp_kernel<<<NS / 8, 256>>>(src_nv1, src_nv2, Esh, Esl, src_inv, NS, NS);
    adp_kernel<<<NT / 8, 256>>>(vna_nv1, vna_nv2, Evh, Evl, vna_inv, NT, NS);
    adp_kernel<<<NT / 8, 256>>>(tgt_nv1, tgt_nv2, Eth, Etl, tgt_inv, NT, NT);

    const int tilesS = (NS + BM - 1) / BM;   // 79
    const int tilesT = (NT + BM - 1) / BM;   // 63
    dim3 xg5((NS + 31) / 32, 4), xg4((NT + 31) / 32, 4);

    // ---- Source GC block (2 residual layers) ----
    for (int i = 0; i < 2; i++) {
        xt_prep<<<xg5, 256>>>(lr + (size_t)i * NS * 128, Xth, Xtl, NS);
        hmma_gemm<<<dim3(tilesS, 1, 2), 256, SMEM_GEMM>>>(A2h, A2l, Esh, Esl, src_inv,
                                                          Xth, Xtl, Yb, NS, NS);
        gc_epilogue_kernel<<<(NS + 7) / 8, 256>>>(Yb, src_W + i * 8192, src_b + i * 64,
                                                  lr + (size_t)i * NS * 128,
                                                  lr + (size_t)(i + 1) * NS * 128, NS);
    }

    // ---- VNA block (3 layers, Ns -> Nt) ----
    for (int i = 0; i < 3; i++) {
        xt_prep<<<xg5, 256>>>(lr + (size_t)i * NS * 128, Xth, Xtl, NS);
        hmma_gemm<<<dim3(tilesT, 1, 2), 256, SMEM_GEMM>>>(A1h, A1l, Evh, Evl, vna_inv,
                                                          Xth, Xtl, Yb, NT, NS);
        gc_epilogue_kernel<<<(NT + 7) / 8, 256>>>(Yb, vna_W + i * 8192, vna_b + i * 64,
                                                  nullptr, semb + (size_t)i * NT * 128, NT);
    }

    // ---- Target GC block with gated fusion ----
    for (int i = 0; i < 3; i++) {
        xt_prep<<<xg4, 256>>>(xtb, Xth, Xtl, NT);
        hmma_gemm<<<dim3(tilesT, 1, 2), 256, SMEM_GEMM>>>(A0h, A0l, Eth, Etl, tgt_inv,
                                                          Xth, Xtl, Yb, NT, NT);
        gc_epilogue_kernel<<<(NT + 7) / 8, 256>>>(Yb, tgt_W + i * 8192, tgt_b + i * 64,
                                                  nullptr, Tb, NT);
        fusion_kernel<<<(NT + 7) / 8, 256>>>(Tb, semb + (size_t)i * NT * 128,
                                             fus_Wt + i * 4096, fus_Ws + i * 4096,
                                             fus_b + i * 64, xtb, NT);
    }

    unpack_kernel<<<(NT * 128 + 255) / 256, 256>>>(xtb, (float*)d_out, NT);
}

// round 6
// speedup vs baseline: 1.1684x; 1.1684x over previous
#include <cuda_runtime.h>
#include <cuda_fp16.h>
#include <math.h>
#include <stdint.h>

#define NT 4000
#define NS 5000
#define LOG2E 1.4426950408889634f

typedef unsigned short u16;

// ===================== scratch =============================================
__device__ __align__(16) u16 g_A0f[16000000];
__device__ __align__(16) u16 g_A1f[20000000];
__device__ __align__(16) u16 g_A2f[25000000];
__device__ __align__(16) u16 g_Es[25000000];
__device__ __align__(16) u16 g_Ev[20000000];
__device__ __align__(16) u16 g_Et[16000000];
__device__ __align__(16) float g_dots[25000000];
__device__ unsigned g_dmax[NS + NT + NT];
__device__ __align__(16) u16 g_Xh[2432000];   // X^T fp16 hi: slots 0-2 = lr (128*NS each), slot3 = xt (128*NT)
__device__ __align__(16) u16 g_Xl[2432000];
__device__ float g_src_inv[NS];
__device__ float g_vna_inv[NT];
__device__ float g_tgt_inv[NT];
__device__ __align__(16) float g_lr[3 * NS * 128];
__device__ __align__(16) float g_semb[3 * NT * 128];
__device__ __align__(16) float g_Y[3100000];
__device__ __align__(16) float g_xt[NT * 128];

// ===================== PTX helpers =========================================
__device__ __forceinline__ uint32_t smem_u32(const void* p) {
    uint32_t a;
    asm("{ .reg .u64 t; cvta.to.shared.u64 t, %1; cvt.u32.u64 %0, t; }" : "=r"(a) : "l"(p));
    return a;
}
#define CP_ASYNC16(saddr, gaddr, sz) \
    asm volatile("cp.async.ca.shared.global [%0], [%1], 16, %2;" :: "r"(saddr), "l"(gaddr), "r"(sz))
#define CP_COMMIT() asm volatile("cp.async.commit_group;" ::: "memory")
#define CP_WAIT1()  asm volatile("cp.async.wait_group 1;" ::: "memory")
#define LDSM4(r, a) \
    asm volatile("ldmatrix.sync.aligned.m8n8.x4.shared.b16 {%0,%1,%2,%3}, [%4];" \
        : "=r"((r)[0]), "=r"((r)[1]), "=r"((r)[2]), "=r"((r)[3]) : "r"(a))
#define MMA_FP16(c, A, b0, b1) \
    asm volatile("mma.sync.aligned.m16n8k16.row.col.f32.f16.f16.f32 " \
        "{%0,%1,%2,%3},{%4,%5,%6,%7},{%8,%9},{%0,%1,%2,%3};" \
        : "+f"((c)[0]), "+f"((c)[1]), "+f"((c)[2]), "+f"((c)[3]) \
        : "r"((A)[0]), "r"((A)[1]), "r"((A)[2]), "r"((A)[3]), "r"(b0), "r"(b1))

__device__ __forceinline__ uint32_t pack_h2(float a, float b) {
    return (uint32_t)__half_as_ushort(__float2half_rn(a)) |
           ((uint32_t)__half_as_ushort(__float2half_rn(b)) << 16);
}
// pack 8 fp32 -> hi/lo fp16 uint4 pair
__device__ __forceinline__ void split8(const float* v, uint4& H, uint4& L) {
    float h[8], l[8];
#pragma unroll
    for (int j = 0; j < 8; j++) {
        h[j] = __half2float(__float2half_rn(v[j]));
        l[j] = v[j] - h[j];
    }
    H.x = pack_h2(v[0] - l[0], v[1] - l[1]); // == fp16(v) exactly
    H.x = pack_h2(h[0], h[1]); H.y = pack_h2(h[2], h[3]);
    H.z = pack_h2(h[4], h[5]); H.w = pack_h2(h[6], h[7]);
    L.x = pack_h2(l[0], l[1]); L.y = pack_h2(l[2], l[3]);
    L.z = pack_h2(l[4], l[5]); L.w = pack_h2(l[6], l[7]);
}

// ===================== small kernels ========================================
__global__ void zero_kernel(unsigned* p, int n) {
    int i = blockIdx.x * blockDim.x + threadIdx.x;
    if (i < n) p[i] = 0u;
}
__global__ void unpack_kernel(const float* __restrict__ xp, float* __restrict__ out, int n) {
    int i = blockIdx.x * blockDim.x + threadIdx.x;
    if (i >= n * 128) return;
    int r = i >> 7, c = i & 127, b = c >> 6, d = c & 63;
    out[((size_t)b * n + r) * 64 + d] = xp[i];
}
__global__ void tofp16_kernel(const float* __restrict__ A, u16* __restrict__ F, int n4) {
    int i = blockIdx.x * blockDim.x + threadIdx.x;
    if (i >= n4) return;
    float4 v = ((const float4*)A)[i];
    uint2 o;
    o.x = pack_h2(v.x * 4096.f, v.y * 4096.f);
    o.y = pack_h2(v.z * 4096.f, v.w * 4096.f);
    ((uint2*)F)[i] = o;
}
// pack [B,n,64] -> [n,128] fp32 + transposed fp16 hi/lo [128,n]
__global__ __launch_bounds__(256)
void pack_prep(const float* __restrict__ x, float* __restrict__ xp,
               u16* __restrict__ Xh, u16* __restrict__ Xl, int n)
{
    __shared__ float t[8][128];
    const int tid = threadIdx.x, r0 = blockIdx.x * 8;
    for (int i = tid; i < 1024; i += 256) {
        int r = i >> 7, c = i & 127, b = c >> 6, d = c & 63;
        float v = x[((size_t)b * n + r0 + r) * 64 + d];
        xp[(size_t)(r0 + r) * 128 + c] = v;
        t[r][c] = v;
    }
    __syncthreads();
    if (tid < 128) {
        float v[8];
#pragma unroll
        for (int j = 0; j < 8; j++) v[j] = t[j][tid];
        uint4 H, L; split8(v, H, L);
        *(uint4*)(Xh + (size_t)tid * n + r0) = H;
        *(uint4*)(Xl + (size_t)tid * n + r0) = L;
    }
}

// ===================== adp: dots + max ======================================
__global__ __launch_bounds__(256)
void adp_dots(const float* __restrict__ nv1, const float* __restrict__ nv2,
              float* __restrict__ D, unsigned* __restrict__ Dmax, int nrows, int ncols)
{
    __shared__ float v1s[8][30];
    __shared__ float part[8][8];
    const int tid = threadIdx.x, r0 = blockIdx.x * 8;
    const int c0 = blockIdx.y * 1280;
    const int cend = min(c0 + 1280, ncols);
    if (tid < 240) v1s[tid / 30][tid % 30] = nv1[(size_t)(r0 + tid / 30) * 30 + tid % 30];
    __syncthreads();
    float mx[8];
#pragma unroll
    for (int r = 0; r < 8; r++) mx[r] = 0.f;
    for (int c = c0 + tid; c < cend; c += 256) {
        float col[30];
#pragma unroll
        for (int q = 0; q < 30; q++) col[q] = nv2[(size_t)q * ncols + c];
#pragma unroll
        for (int r = 0; r < 8; r++) {
            float dot = 0.f;
#pragma unroll
            for (int q = 0; q < 30; q++) dot = fmaf(v1s[r][q], col[q], dot);
            float dp = fmaxf(dot, 0.f);
            D[(size_t)(r0 + r) * ncols + c] = dp;
            mx[r] = fmaxf(mx[r], dp);
        }
    }
    const int lane = tid & 31, wid = tid >> 5;
#pragma unroll
    for (int r = 0; r < 8; r++) {
        float v = mx[r];
#pragma unroll
        for (int off = 16; off > 0; off >>= 1)
            v = fmaxf(v, __shfl_down_sync(0xffffffffu, v, off));
        if (lane == 0) part[wid][r] = v;
    }
    __syncthreads();
    if (tid < 8) {
        float v = part[0][tid];
#pragma unroll
        for (int w = 1; w < 8; w++) v = fmaxf(v, part[w][tid]);
        atomicMax(Dmax + r0 + tid, __float_as_uint(v));  // v >= 0: bit-order == float-order
    }
}

// ===================== adp: exp + fp16 E + invsum ===========================
__global__ __launch_bounds__(256)
void adp_finish(const float* __restrict__ D, const unsigned* __restrict__ Dmax,
                u16* __restrict__ E, float* __restrict__ inv, int nrows, int ncols)
{
    __shared__ float part[8][8];
    const int tid = threadIdx.x, r0 = blockIdx.x * 8;
    float M[8], ps[8];
#pragma unroll
    for (int r = 0; r < 8; r++) { M[r] = __uint_as_float(Dmax[r0 + r]); ps[r] = 0.f; }
    for (int c = tid; c < ncols; c += 256) {
#pragma unroll
        for (int r = 0; r < 8; r++) {
            size_t idx = (size_t)(r0 + r) * ncols + c;
            float t = (D[idx] - M[r]) * LOG2E;
            float e;
            asm("ex2.approx.f32 %0, %1;" : "=f"(e) : "f"(t));
            E[idx] = __half_as_ushort(__float2half_rn(e));
            ps[r] += e;
        }
    }
    const int lane = tid & 31, wid = tid >> 5;
#pragma unroll
    for (int r = 0; r < 8; r++) {
        float v = ps[r];
#pragma unroll
        for (int off = 16; off > 0; off >>= 1) v += __shfl_down_sync(0xffffffffu, v, off);
        if (lane == 0) part[wid][r] = v;
    }
    __syncthreads();
    if (tid < 8) {
        float s = 0.f;
#pragma unroll
        for (int w = 0; w < 8; w++) s += part[w][tid];
        inv[r0 + tid] = 1.0f / s;
    }
}

// ===================== fp16 2-pass HMMA GEMM ================================
// Y[slot] = A_z[n,m] @ X_y[m,128]; z=0 dense(prescaled 4096), z=1 adaptive E.
#define BM 64
#define GKT 64
#define STAGE_B 40960   // A 8K | Bh 16K | Bl 16K
#define SMEM_GEMM (2 * STAGE_B)

__device__ __forceinline__ void stage_load2(
    uint32_t sdst, const u16* __restrict__ Af,
    const u16* __restrict__ Xh, const u16* __restrict__ Xl,
    int row0, int kbase, int n, int m, int tid)
{
#pragma unroll
    for (int t = 0; t < 2; t++) {
        int id = tid + t * 256;
        int r = id >> 3, kc = id & 7;
        int gr = row0 + r, gk = kbase + kc * 8;
        bool v = (gr < n) && (gk < m);
        size_t gi = (size_t)(v ? gr : 0) * m + (v ? gk : 0);
        uint32_t off = r * 128 + kc * 16;
        uint32_t sw = off ^ ((off >> 3) & 0x70);
        CP_ASYNC16(sdst + sw, Af + gi, v ? 16u : 0u);
    }
#pragma unroll
    for (int t = 0; t < 4; t++) {
        int id = tid + t * 256;
        int r = id >> 3, kc = id & 7;
        int gk = kbase + kc * 8;
        bool v = (gk < m);
        size_t gi = (size_t)r * m + (v ? gk : 0);
        uint32_t off = r * 128 + kc * 16;
        uint32_t sw = off ^ ((off >> 3) & 0x70);
        unsigned sz = v ? 16u : 0u;
        CP_ASYNC16(sdst + 8192 + sw, Xh + gi, sz);
        CP_ASYNC16(sdst + 24576 + sw, Xl + gi, sz);
    }
}

__global__ __launch_bounds__(256, 2)
void hmma_gemm2(const u16* __restrict__ Af, const u16* __restrict__ Ef,
                const float* __restrict__ invsum,
                const u16* __restrict__ Xh, const u16* __restrict__ Xl,
                float* __restrict__ Y, int n, int m)
{
    extern __shared__ __align__(128) char smem[];
    const uint32_t sb = smem_u32(smem);
    const int tid = threadIdx.x, lane = tid & 31, wid = tid >> 5;
    const int wm = wid >> 2, wn = wid & 3;
    const u16* __restrict__ A = blockIdx.z ? Ef : Af;
    const u16* __restrict__ Xhp = Xh + (size_t)blockIdx.y * 128 * m;
    const u16* __restrict__ Xlp = Xl + (size_t)blockIdx.y * 128 * m;
    const int row0 = blockIdx.x * BM;
    const int ktn = (m + GKT - 1) / GKT;

    float acc[2][4][4];
#pragma unroll
    for (int i = 0; i < 2; i++)
#pragma unroll
        for (int j = 0; j < 4; j++)
#pragma unroll
            for (int q = 0; q < 4; q++) acc[i][j][q] = 0.f;

    uint32_t arow[2], axor[2];
#pragma unroll
    for (int mt = 0; mt < 2; mt++) {
        int r = wm * 32 + mt * 16 + (lane & 7) + (((lane >> 3) & 1) << 3);
        arow[mt] = (uint32_t)r * 128;
        axor[mt] = ((uint32_t)r * 16) & 0x70;
    }
    const uint32_t akbs = ((lane >> 4) & 1) * 16;
    uint32_t brow[2], bxor[2];
#pragma unroll
    for (int bt = 0; bt < 2; bt++) {
        int r = wn * 32 + bt * 16 + (lane & 7) + (((lane >> 4) & 1) << 3);
        brow[bt] = (uint32_t)r * 128;
        bxor[bt] = ((uint32_t)r * 16) & 0x70;
    }
    const uint32_t bkbs = ((lane >> 3) & 1) * 16;

    stage_load2(sb, A, Xhp, Xlp, row0, 0, n, m, tid);
    CP_COMMIT();

    for (int kt = 0; kt < ktn; kt++) {
        if (kt + 1 < ktn)
            stage_load2(sb + ((kt + 1) & 1) * STAGE_B, A, Xhp, Xlp, row0, (kt + 1) * GKT, n, m, tid);
        CP_COMMIT();
        CP_WAIT1();
        __syncthreads();
        const uint32_t stb = sb + (kt & 1) * STAGE_B;
#pragma unroll
        for (int ks = 0; ks < 4; ks++) {
            const uint32_t kb = ks * 32;
            uint32_t fa[2][4], fbh[2][4], fbl[2][4];
#pragma unroll
            for (int mt = 0; mt < 2; mt++)
                LDSM4(fa[mt], stb + arow[mt] + ((kb + akbs) ^ axor[mt]));
#pragma unroll
            for (int bt = 0; bt < 2; bt++) {
                uint32_t bd = stb + 8192 + brow[bt] + ((kb + bkbs) ^ bxor[bt]);
                LDSM4(fbh[bt], bd);
                LDSM4(fbl[bt], bd + 16384);
            }
#pragma unroll
            for (int mt = 0; mt < 2; mt++)
#pragma unroll
                for (int nt = 0; nt < 4; nt++) {
                    const int g = nt >> 1, h = (nt & 1) << 1;
                    MMA_FP16(acc[mt][nt], fa[mt], fbh[g][h], fbh[g][h + 1]);
                    MMA_FP16(acc[mt][nt], fa[mt], fbl[g][h], fbl[g][h + 1]);
                }
        }
        __syncthreads();
    }

    float* __restrict__ Yz = Y + (size_t)(blockIdx.y * 2 + blockIdx.z) * n * 128;
#pragma unroll
    for (int mt = 0; mt < 2; mt++) {
        int gr0 = row0 + wm * 32 + mt * 16 + (lane >> 2);
        int gr1 = gr0 + 8;
        float s0, s1;
        if (blockIdx.z) {
            s0 = (gr0 < n) ? invsum[gr0] : 0.f;
            s1 = (gr1 < n) ? invsum[gr1] : 0.f;
        } else {
            s0 = s1 = 2.44140625e-4f;  // 1/4096
        }
#pragma unroll
        for (int nt = 0; nt < 4; nt++) {
            int col = wn * 32 + nt * 8 + ((lane & 3) << 1);
            if (gr0 < n)
                *(float2*)(Yz + (size_t)gr0 * 128 + col) =
                    make_float2(acc[mt][nt][0] * s0, acc[mt][nt][1] * s0);
            if (gr1 < n)
                *(float2*)(Yz + (size_t)gr1 * 128 + col) =
                    make_float2(acc[mt][nt][2] * s1, acc[mt][nt][3] * s1);
        }
    }
}

// ===================== source epilogue (+residual, +X^T fp16 out) ===========
__global__ __launch_bounds__(256)
void epi_src(const float* __restrict__ Y, const float* __restrict__ W,
             const float* __restrict__ bias, const float* __restrict__ prev,
             float* __restrict__ out, u16* __restrict__ Xh, u16* __restrict__ Xl, int n)
{
    __shared__ float Ws[128][64];
    __shared__ float Y1s[8][128];
    __shared__ float Y2s[8][128];
    __shared__ float oS[8][128];
    const int tid = threadIdx.x, r0 = blockIdx.x * 8;
    for (int i = tid; i < 8192; i += 256) Ws[i >> 6][i & 63] = W[i];
    const float* __restrict__ Y2 = Y + (size_t)n * 128;
    for (int i = tid; i < 1024; i += 256) {
        int r = i >> 7, c = i & 127;
        size_t gi = (size_t)(r0 + r) * 128 + c;
        Y1s[r][c] = Y[gi]; Y2s[r][c] = Y2[gi];
    }
    __syncthreads();
    const int c = tid & 127, rg = tid >> 7, d = c & 63, b64 = c & 64;
    const float bv = bias[d];
    for (int rr = rg; rr < 8; rr += 2) {
        float acc = bv;
#pragma unroll
        for (int k = 0; k < 64; k++) {
            acc = fmaf(Y1s[rr][b64 + k], Ws[k][d], acc);
            acc = fmaf(Y2s[rr][b64 + k], Ws[64 + k][d], acc);
        }
        float g = prev[(size_t)(r0 + rr) * 128 + c] + fmaxf(acc, 0.f);
        out[(size_t)(r0 + rr) * 128 + c] = g;
        oS[rr][c] = g;
    }
    __syncthreads();
    if (tid < 128) {
        float v[8];
#pragma unroll
        for (int j = 0; j < 8; j++) v[j] = oS[j][tid];
        uint4 H, L; split8(v, H, L);
        *(uint4*)(Xh + (size_t)tid * n + r0) = H;
        *(uint4*)(Xl + (size_t)tid * n + r0) = L;
    }
}

// ===================== VNA epilogue (batched over 3 layers) =================
__global__ __launch_bounds__(256)
void epi_vna(const float* __restrict__ Y, const float* __restrict__ W,
             const float* __restrict__ bias, float* __restrict__ semb, int n)
{
    __shared__ float Ws[128][64];
    __shared__ float Y1s[8][128];
    __shared__ float Y2s[8][128];
    const int tid = threadIdx.x, r0 = blockIdx.x * 8, y = blockIdx.y;
    const float* __restrict__ Wp = W + y * 8192;
    const float* __restrict__ Y1 = Y + (size_t)(2 * y) * n * 128;
    const float* __restrict__ Y2 = Y1 + (size_t)n * 128;
    float* __restrict__ out = semb + (size_t)y * n * 128;
    for (int i = tid; i < 8192; i += 256) Ws[i >> 6][i & 63] = Wp[i];
    for (int i = tid; i < 1024; i += 256) {
        int r = i >> 7, c = i & 127;
        size_t gi = (size_t)(r0 + r) * 128 + c;
        Y1s[r][c] = Y1[gi]; Y2s[r][c] = Y2[gi];
    }
    __syncthreads();
    const int c = tid & 127, rg = tid >> 7, d = c & 63, b64 = c & 64;
    const float bv = bias[y * 64 + d];
    for (int rr = rg; rr < 8; rr += 2) {
        float acc = bv;
#pragma unroll
        for (int k = 0; k < 64; k++) {
            acc = fmaf(Y1s[rr][b64 + k], Ws[k][d], acc);
            acc = fmaf(Y2s[rr][b64 + k], Ws[64 + k][d], acc);
        }
        out[(size_t)(r0 + rr) * 128 + c] = fmaxf(acc, 0.f);
    }
}

// ===================== target epilogue + gated fusion (+X^T out) ============
#define SMEM_TGT 49152
__global__ __launch_bounds__(256)
void epi_tgt(const float* __restrict__ Y, const float* __restrict__ W,
             const float* __restrict__ bias, const float* __restrict__ S,
             const float* __restrict__ fWt, const float* __restrict__ fWs,
             const float* __restrict__ fb, float* __restrict__ xt,
             u16* __restrict__ Xh, u16* __restrict__ Xl, int n)
{
    extern __shared__ __align__(16) char dsm[];
    float* Wbuf = (float*)dsm;                              // 32KB
    float (*Y1s)[128] = (float(*)[128])(dsm + 32768);
    float (*Y2s)[128] = (float(*)[128])(dsm + 36864);
    float (*tS)[128]  = (float(*)[128])(dsm + 40960);
    float (*sS)[128]  = (float(*)[128])(dsm + 45056);
    const int tid = threadIdx.x, r0 = blockIdx.x * 8;
    for (int i = tid; i < 8192; i += 256) Wbuf[i] = W[i];
    const float* __restrict__ Y2 = Y + (size_t)n * 128;
    for (int i = tid; i < 1024; i += 256) {
        int r = i >> 7, c = i & 127;
        size_t gi = (size_t)(r0 + r) * 128 + c;
        Y1s[r][c] = Y[gi]; Y2s[r][c] = Y2[gi];
        sS[r][c] = S[gi];
    }
    __syncthreads();
    const int c = tid & 127, rg = tid >> 7, d = c & 63, b64 = c & 64;
    const float bv = bias[d];
    for (int rr = rg; rr < 8; rr += 2) {
        float acc = bv;
#pragma unroll
        for (int k = 0; k < 64; k++) {
            acc = fmaf(Y1s[rr][b64 + k], Wbuf[k * 64 + d], acc);
            acc = fmaf(Y2s[rr][b64 + k], Wbuf[(64 + k) * 64 + d], acc);
        }
        tS[rr][c] = fmaxf(acc, 0.f);
    }
    __syncthreads();
    for (int i = tid; i < 4096; i += 256) { Wbuf[i] = fWt[i]; Wbuf[4096 + i] = fWs[i]; }
    __syncthreads();
    const float fbv = fb[d];
    for (int rr = rg; rr < 8; rr += 2) {
        float za = fbv;
#pragma unroll
        for (int k = 0; k < 64; k++) {
            za = fmaf(tS[rr][b64 + k], Wbuf[k * 64 + d], za);
            za = fmaf(sS[rr][b64 + k], Wbuf[4096 + k * 64 + d], za);
        }
        float z = 1.f / (1.f + expf(-za));
        float tv = tS[rr][c], sv = sS[rr][c];
        size_t gi = (size_t)(r0 + rr) * 128 + c;
        float nx = xt[gi] + z * tv + (1.f - z) * sv;
        xt[gi] = nx;
        Y1s[rr][c] = nx;   // reuse as transpose staging
    }
    __syncthreads();
    if (Xh && tid < 128) {
        float v[8];
#pragma unroll
        for (int j = 0; j < 8; j++) v[j] = Y1s[j][tid];
        uint4 H, L; split8(v, H, L);
        *(uint4*)(Xh + (size_t)tid * n + r0) = H;
        *(uint4*)(Xl + (size_t)tid * n + r0) = L;
    }
}

// ===================== launcher =============================================
extern "C" void kernel_launch(void* const* d_in, const int* in_sizes, int n_in,
                              void* d_out, int out_size)
{
    (void)in_sizes; (void)n_in; (void)out_size;
    const float* A0      = (const float*)d_in[0];
    const float* A1      = (const float*)d_in[1];
    const float* A2      = (const float*)d_in[2];
    const float* x0      = (const float*)d_in[3];
    const float* x1      = (const float*)d_in[4];
    const float* src_nv1 = (const float*)d_in[5];
    const float* src_nv2 = (const float*)d_in[6];
    const float* src_W   = (const float*)d_in[7];
    const float* src_b   = (const float*)d_in[8];
    const float* vna_nv1 = (const float*)d_in[9];
    const float* vna_nv2 = (const float*)d_in[10];
    const float* vna_W   = (const float*)d_in[11];
    const float* vna_b   = (const float*)d_in[12];
    const float* tgt_nv1 = (const float*)d_in[13];
    const float* tgt_nv2 = (const float*)d_in[14];
    const float* tgt_W   = (const float*)d_in[15];
    const float* tgt_b   = (const float*)d_in[16];
    const float* fus_Wt  = (const float*)d_in[17];
    const float* fus_Ws  = (const float*)d_in[18];
    const float* fus_b   = (const float*)d_in[19];

    u16 *A0f, *A1f, *A2f, *Es, *Ev, *Et, *Xh, *Xl;
    float *dots, *src_inv, *vna_inv, *tgt_inv, *lr, *semb, *Yb, *xtb;
    unsigned* dmax;
    cudaGetSymbolAddress((void**)&A0f, g_A0f);
    cudaGetSymbolAddress((void**)&A1f, g_A1f);
    cudaGetSymbolAddress((void**)&A2f, g_A2f);
    cudaGetSymbolAddress((void**)&Es, g_Es);
    cudaGetSymbolAddress((void**)&Ev, g_Ev);
    cudaGetSymbolAddress((void**)&Et, g_Et);
    cudaGetSymbolAddress((void**)&Xh, g_Xh);
    cudaGetSymbolAddress((void**)&Xl, g_Xl);
    cudaGetSymbolAddress((void**)&dots, g_dots);
    cudaGetSymbolAddress((void**)&dmax, g_dmax);
    cudaGetSymbolAddress((void**)&src_inv, g_src_inv);
    cudaGetSymbolAddress((void**)&vna_inv, g_vna_inv);
    cudaGetSymbolAddress((void**)&tgt_inv, g_tgt_inv);
    cudaGetSymbolAddress((void**)&lr, g_lr);
    cudaGetSymbolAddress((void**)&semb, g_semb);
    cudaGetSymbolAddress((void**)&Yb, g_Y);
    cudaGetSymbolAddress((void**)&xtb, g_xt);

    cudaFuncSetAttribute(hmma_gemm2, cudaFuncAttributeMaxDynamicSharedMemorySize, SMEM_GEMM);
    cudaFuncSetAttribute(epi_tgt, cudaFuncAttributeMaxDynamicSharedMemorySize, SMEM_TGT);

    const size_t SLOT = (size_t)128 * NS;           // X^T slot stride
    u16 *Xh3 = Xh + 3 * SLOT, *Xl3 = Xl + 3 * SLOT; // xt slot

    // packs + dense conversions
    pack_prep<<<NS / 8, 256>>>(x1, lr, Xh, Xl, NS);
    pack_prep<<<NT / 8, 256>>>(x0, xtb, Xh3, Xl3, NT);
    tofp16_kernel<<<(NT * NT / 4 + 255) / 256, 256>>>(A0, A0f, NT * NT / 4);
    tofp16_kernel<<<(NT * NS / 4 + 255) / 256, 256>>>(A1, A1f, NT * NS / 4);
    tofp16_kernel<<<(NS * NS / 4 + 255) / 256, 256>>>(A2, A2f, NS * NS / 4);

    // adaptive adjacencies
    zero_kernel<<<(NS + 2 * NT + 255) / 256, 256>>>(dmax, NS + 2 * NT);
    adp_dots<<<dim3(NS / 8, (NS + 1279) / 1280), 256>>>(src_nv1, src_nv2, dots, dmax, NS, NS);
    adp_finish<<<NS / 8, 256>>>(dots, dmax, Es, src_inv, NS, NS);
    adp_dots<<<dim3(NT / 8, (NS + 1279) / 1280), 256>>>(vna_nv1, vna_nv2, dots, dmax + NS, NT, NS);
    adp_finish<<<NT / 8, 256>>>(dots, dmax + NS, Ev, vna_inv, NT, NS);
    adp_dots<<<dim3(NT / 8, (NT + 1279) / 1280), 256>>>(tgt_nv1, tgt_nv2, dots, dmax + NS + NT, NT, NT);
    adp_finish<<<NT / 8, 256>>>(dots, dmax + NS + NT, Et, tgt_inv, NT, NT);

    const int tilesS = (NS + BM - 1) / BM, tilesT = (NT + BM - 1) / BM;

    // ---- Source GC block (2 residual layers) ----
    for (int i = 0; i < 2; i++) {
        hmma_gemm2<<<dim3(tilesS, 1, 2), 256, SMEM_GEMM>>>(A2f, Es, src_inv,
            Xh + i * SLOT, Xl + i * SLOT, Yb, NS, NS);
        epi_src<<<NS / 8, 256>>>(Yb, src_W + i * 8192, src_b + i * 64,
            lr + (size_t)i * NS * 128, lr + (size_t)(i + 1) * NS * 128,
            Xh + (i + 1) * SLOT, Xl + (i + 1) * SLOT, NS);
    }

    // ---- VNA block: 3 layers batched ----
    hmma_gemm2<<<dim3(tilesT, 3, 2), 256, SMEM_GEMM>>>(A1f, Ev, vna_inv, Xh, Xl, Yb, NT, NS);
    epi_vna<<<dim3(NT / 8, 3), 256>>>(Yb, vna_W, vna_b, semb, NT);

    // ---- Target GC block with gated fusion ----
    for (int i = 0; i < 3; i++) {
        hmma_gemm2<<<dim3(tilesT, 1, 2), 256, SMEM_GEMM>>>(A0f, Et, tgt_inv, Xh3, Xl3, Yb, NT, NT);
        epi_tgt<<<NT / 8, 256, SMEM_TGT>>>(Yb, tgt_W + i * 8192, tgt_b + i * 64,
            semb + (size_t)i * NT * 128, fus_Wt + i * 4096, fus_Ws + i * 4096,
            fus_b + i * 64, xtb, (i < 2) ? Xh3 : nullptr, (i < 2) ? Xl3 : nullptr, NT);
    }

    unpack_kernel<<<(NT * 128 + 255) / 256, 256>>>(xtb, (float*)d_out, NT);
}

// round 7
// speedup vs baseline: 1.8670x; 1.5979x over previous
#include <cuda_runtime.h>
#include <cuda_fp16.h>
#include <math.h>
#include <stdint.h>

#define NT 4000
#define NS 5000
#define LOG2E 1.4426950408889634f

typedef unsigned short u16;

// ===================== scratch =============================================
__device__ __align__(16) u16 g_A0f[16000000];
__device__ __align__(16) u16 g_A1f[20000000];
__device__ __align__(16) u16 g_A2f[25000000];
__device__ __align__(16) u16 g_Es[25000000];
__device__ __align__(16) u16 g_Ev[20000000];
__device__ __align__(16) u16 g_Et[16000000];
__device__ __align__(16) u16 g_Xf[2432000];   // X^T fp16: slots 0-2 = lr (128*NS each), slot3 = xt (128*NT)
__device__ float g_src_inv[NS];
__device__ float g_vna_inv[NT];
__device__ float g_tgt_inv[NT];
__device__ __align__(16) float g_lr[3 * NS * 128];
__device__ __align__(16) float g_semb[3 * NT * 128];
__device__ __align__(16) float g_Y[3100000];
__device__ __align__(16) float g_xt[NT * 128];

// ===================== PTX helpers =========================================
__device__ __forceinline__ uint32_t smem_u32(const void* p) {
    uint32_t a;
    asm("{ .reg .u64 t; cvta.to.shared.u64 t, %1; cvt.u32.u64 %0, t; }" : "=r"(a) : "l"(p));
    return a;
}
#define CP_ASYNC16(saddr, gaddr, sz) \
    asm volatile("cp.async.ca.shared.global [%0], [%1], 16, %2;" :: "r"(saddr), "l"(gaddr), "r"(sz))
#define CP_COMMIT() asm volatile("cp.async.commit_group;" ::: "memory")
#define CP_WAIT1()  asm volatile("cp.async.wait_group 1;" ::: "memory")
#define LDSM4(r, a) \
    asm volatile("ldmatrix.sync.aligned.m8n8.x4.shared.b16 {%0,%1,%2,%3}, [%4];" \
        : "=r"((r)[0]), "=r"((r)[1]), "=r"((r)[2]), "=r"((r)[3]) : "r"(a))
#define MMA_FP16(c, A, b0, b1) \
    asm volatile("mma.sync.aligned.m16n8k16.row.col.f32.f16.f16.f32 " \
        "{%0,%1,%2,%3},{%4,%5,%6,%7},{%8,%9},{%0,%1,%2,%3};" \
        : "+f"((c)[0]), "+f"((c)[1]), "+f"((c)[2]), "+f"((c)[3]) \
        : "r"((A)[0]), "r"((A)[1]), "r"((A)[2]), "r"((A)[3]), "r"(b0), "r"(b1))

__device__ __forceinline__ uint32_t pack_h2(float a, float b) {
    return (uint32_t)__half_as_ushort(__float2half_rn(a)) |
           ((uint32_t)__half_as_ushort(__float2half_rn(b)) << 16);
}
__device__ __forceinline__ uint4 pack8(const float* v) {
    uint4 H;
    H.x = pack_h2(v[0], v[1]); H.y = pack_h2(v[2], v[3]);
    H.z = pack_h2(v[4], v[5]); H.w = pack_h2(v[6], v[7]);
    return H;
}

// ===================== small kernels ========================================
__global__ void unpack_kernel(const float* __restrict__ xp, float* __restrict__ out, int n) {
    int i = blockIdx.x * blockDim.x + threadIdx.x;
    if (i >= n * 128) return;
    int r = i >> 7, c = i & 127, b = c >> 6, d = c & 63;
    out[((size_t)b * n + r) * 64 + d] = xp[i];
}
__global__ void tofp16_kernel(const float* __restrict__ A, u16* __restrict__ F, int n4) {
    int i = blockIdx.x * blockDim.x + threadIdx.x;
    if (i >= n4) return;
    float4 v = ((const float4*)A)[i];
    uint2 o;
    o.x = pack_h2(v.x * 4096.f, v.y * 4096.f);
    o.y = pack_h2(v.z * 4096.f, v.w * 4096.f);
    ((uint2*)F)[i] = o;
}
// pack [B,n,64] -> [n,128] fp32 + transposed fp16 [128,n]
__global__ __launch_bounds__(256)
void pack_prep(const float* __restrict__ x, float* __restrict__ xp,
               u16* __restrict__ Xf, int n)
{
    __shared__ float t[8][128];
    const int tid = threadIdx.x, r0 = blockIdx.x * 8;
    for (int i = tid; i < 1024; i += 256) {
        int r = i >> 7, c = i & 127, b = c >> 6, d = c & 63;
        float v = x[((size_t)b * n + r0 + r) * 64 + d];
        xp[(size_t)(r0 + r) * 128 + c] = v;
        t[r][c] = v;
    }
    __syncthreads();
    if (tid < 128) {
        float v[8];
#pragma unroll
        for (int j = 0; j < 8; j++) v[j] = t[j][tid];
        *(uint4*)(Xf + (size_t)tid * n + r0) = pack8(v);
    }
}

// ===================== fused adaptive adjacency =============================
// One CTA = 8 rows. Dots buffered in dynamic smem; row max in-block;
// E = exp2f16x2((d-max)*log2e) fp16; inv = 1/rowsum (fp32, deterministic).
__global__ __launch_bounds__(256)
void adp_fused(const float* __restrict__ nv1, const float* __restrict__ nv2,
               u16* __restrict__ E, float* __restrict__ inv, int ncols)
{
    extern __shared__ float ds[];      // 8 * ncols floats
    __shared__ float v1s[8][30];
    __shared__ float red[8][8];
    __shared__ float Mrow[8];
    const int tid = threadIdx.x, r0 = blockIdx.x * 8;
    const int lane = tid & 31, wrp = tid >> 5;
    if (tid < 240) v1s[tid / 30][tid % 30] = nv1[(size_t)(r0 + tid / 30) * 30 + tid % 30];
    __syncthreads();

    float mx[8];
#pragma unroll
    for (int r = 0; r < 8; r++) mx[r] = 0.f;
    for (int c = tid; c < ncols; c += 256) {
        float col[30];
#pragma unroll
        for (int q = 0; q < 30; q++) col[q] = nv2[(size_t)q * ncols + c];
#pragma unroll
        for (int r = 0; r < 8; r++) {
            float dot = 0.f;
#pragma unroll
            for (int q = 0; q < 30; q++) dot = fmaf(v1s[r][q], col[q], dot);
            float dp = fmaxf(dot, 0.f);
            ds[r * ncols + c] = dp;
            mx[r] = fmaxf(mx[r], dp);
        }
    }
#pragma unroll
    for (int r = 0; r < 8; r++) {
        float v = mx[r];
#pragma unroll
        for (int off = 16; off > 0; off >>= 1)
            v = fmaxf(v, __shfl_down_sync(0xffffffffu, v, off));
        if (lane == 0) red[wrp][r] = v;
    }
    __syncthreads();
    if (tid < 8) {
        float v = red[0][tid];
#pragma unroll
        for (int w = 1; w < 8; w++) v = fmaxf(v, red[w][tid]);
        Mrow[tid] = v;
    }
    __syncthreads();

    float M[8], ps[8];
#pragma unroll
    for (int r = 0; r < 8; r++) { M[r] = Mrow[r]; ps[r] = 0.f; }
    for (int c = tid * 2; c < ncols; c += 512) {
#pragma unroll
        for (int r = 0; r < 8; r++) {
            size_t idx = (size_t)(r0 + r) * ncols + c;
            float t0 = (ds[r * ncols + c]     - M[r]) * LOG2E;
            float t1 = (ds[r * ncols + c + 1] - M[r]) * LOG2E;
            __half2 tin = __floats2half2_rn(t0, t1);
            uint32_t ti = *(uint32_t*)&tin, eo;
            asm("ex2.approx.f16x2 %0, %1;" : "=r"(eo) : "r"(ti));
            *(uint32_t*)(E + idx) = eo;
            float2 ef = __half22float2(*(__half2*)&eo);
            ps[r] += ef.x + ef.y;
        }
    }
#pragma unroll
    for (int r = 0; r < 8; r++) {
        float v = ps[r];
#pragma unroll
        for (int off = 16; off > 0; off >>= 1) v += __shfl_down_sync(0xffffffffu, v, off);
        if (lane == 0) red[wrp][r] = v;
    }
    __syncthreads();
    if (tid < 8) {
        float s = 0.f;
#pragma unroll
        for (int w = 0; w < 8; w++) s += red[w][tid];
        inv[r0 + tid] = 1.0f / s;
    }
}

// ===================== fp16 single-pass HMMA GEMM ===========================
// 64x64 tile, 128 threads (4 warps 2x2, warp tile 32x32), KT=64, double-buffered.
// grid: x = rowtiles*2 (bit0 = N-half), y = X slot, z = support (0 dense, 1 adaptive)
#define GKT 64
#define STAGE_B 16384   // A 8K | B 8K
#define SMEM_GEMM (2 * STAGE_B)

__device__ __forceinline__ void stage_load3(
    uint32_t sdst, const u16* __restrict__ Ag, const u16* __restrict__ Bg,
    int row0, int kbase, int n, int m, int tid)
{
#pragma unroll
    for (int t = 0; t < 4; t++) {
        int id = tid + t * 128;
        int r = id >> 3, kc = id & 7;
        int gr = row0 + r, gk = kbase + kc * 8;
        bool v = (gr < n) && (gk < m);
        size_t gi = (size_t)(v ? gr : 0) * m + (v ? gk : 0);
        uint32_t off = r * 128 + kc * 16;
        uint32_t sw = off ^ ((off >> 3) & 0x70);
        CP_ASYNC16(sdst + sw, Ag + gi, v ? 16u : 0u);
    }
#pragma unroll
    for (int t = 0; t < 4; t++) {
        int id = tid + t * 128;
        int r = id >> 3, kc = id & 7;
        int gk = kbase + kc * 8;
        bool v = (gk < m);
        size_t gi = (size_t)r * m + (v ? gk : 0);
        uint32_t off = r * 128 + kc * 16;
        uint32_t sw = off ^ ((off >> 3) & 0x70);
        CP_ASYNC16(sdst + 8192 + sw, Bg + gi, v ? 16u : 0u);
    }
}

__global__ __launch_bounds__(128, 4)
void hmma_gemm3(const u16* __restrict__ Af, const u16* __restrict__ Ef,
                const float* __restrict__ invsum,
                const u16* __restrict__ Xf,
                float* __restrict__ Y, int n, int m)
{
    extern __shared__ __align__(128) char smem[];
    const uint32_t sb = smem_u32(smem);
    const int tid = threadIdx.x, lane = tid & 31, wid = tid >> 5;
    const int wm = wid >> 1, wn = wid & 1;
    const int tile = blockIdx.x >> 1, nh = blockIdx.x & 1;
    const int row0 = tile * 64, col0 = nh * 64;
    const u16* __restrict__ A = blockIdx.z ? Ef : Af;
    const u16* __restrict__ B = Xf + ((size_t)blockIdx.y * 128 + col0) * m;
    const int ktn = (m + GKT - 1) / GKT;

    float acc[2][4][4];
#pragma unroll
    for (int i = 0; i < 2; i++)
#pragma unroll
        for (int j = 0; j < 4; j++)
#pragma unroll
            for (int q = 0; q < 4; q++) acc[i][j][q] = 0.f;

    uint32_t arow[2], axor[2];
#pragma unroll
    for (int mt = 0; mt < 2; mt++) {
        int r = wm * 32 + mt * 16 + (lane & 7) + (((lane >> 3) & 1) << 3);
        arow[mt] = (uint32_t)r * 128;
        axor[mt] = ((uint32_t)r * 16) & 0x70;
    }
    const uint32_t akbs = ((lane >> 4) & 1) * 16;
    uint32_t brow[2], bxor[2];
#pragma unroll
    for (int bt = 0; bt < 2; bt++) {
        int r = wn * 32 + bt * 16 + (lane & 7) + (((lane >> 4) & 1) << 3);
        brow[bt] = (uint32_t)r * 128;
        bxor[bt] = ((uint32_t)r * 16) & 0x70;
    }
    const uint32_t bkbs = ((lane >> 3) & 1) * 16;

    stage_load3(sb, A, B, row0, 0, n, m, tid);
    CP_COMMIT();

    for (int kt = 0; kt < ktn; kt++) {
        if (kt + 1 < ktn)
            stage_load3(sb + ((kt + 1) & 1) * STAGE_B, A, B, row0, (kt + 1) * GKT, n, m, tid);
        CP_COMMIT();
        CP_WAIT1();
        __syncthreads();
        const uint32_t stb = sb + (kt & 1) * STAGE_B;
#pragma unroll
        for (int ks = 0; ks < 4; ks++) {
            const uint32_t kb = ks * 32;
            uint32_t fa[2][4], fb[2][4];
#pragma unroll
            for (int mt = 0; mt < 2; mt++)
                LDSM4(fa[mt], stb + arow[mt] + ((kb + akbs) ^ axor[mt]));
#pragma unroll
            for (int bt = 0; bt < 2; bt++)
                LDSM4(fb[bt], stb + 8192 + brow[bt] + ((kb + bkbs) ^ bxor[bt]));
#pragma unroll
            for (int mt = 0; mt < 2; mt++)
#pragma unroll
                for (int nt = 0; nt < 4; nt++) {
                    const int g = nt >> 1, h = (nt & 1) << 1;
                    MMA_FP16(acc[mt][nt], fa[mt], fb[g][h], fb[g][h + 1]);
                }
        }
        __syncthreads();
    }

    float* __restrict__ Yz = Y + (size_t)(blockIdx.y * 2 + blockIdx.z) * n * 128;
#pragma unroll
    for (int mt = 0; mt < 2; mt++) {
        int gr0 = row0 + wm * 32 + mt * 16 + (lane >> 2);
        int gr1 = gr0 + 8;
        float s0, s1;
        if (blockIdx.z) {
            s0 = (gr0 < n) ? invsum[gr0] : 0.f;
            s1 = (gr1 < n) ? invsum[gr1] : 0.f;
        } else {
            s0 = s1 = 2.44140625e-4f;  // 1/4096
        }
#pragma unroll
        for (int nt = 0; nt < 4; nt++) {
            int col = col0 + wn * 32 + nt * 8 + ((lane & 3) << 1);
            if (gr0 < n)
                *(float2*)(Yz + (size_t)gr0 * 128 + col) =
                    make_float2(acc[mt][nt][0] * s0, acc[mt][nt][1] * s0);
            if (gr1 < n)
                *(float2*)(Yz + (size_t)gr1 * 128 + col) =
                    make_float2(acc[mt][nt][2] * s1, acc[mt][nt][3] * s1);
        }
    }
}

// ===================== source epilogue (+residual, +X^T fp16 out) ===========
__global__ __launch_bounds__(256)
void epi_src(const float* __restrict__ Y, const float* __restrict__ W,
             const float* __restrict__ bias, const float* __restrict__ prev,
             float* __restrict__ out, u16* __restrict__ Xf, int n)
{
    __shared__ float Ws[128][64];
    __shared__ float Y1s[8][128];
    __shared__ float Y2s[8][128];
    __shared__ float oS[8][128];
    const int tid = threadIdx.x, r0 = blockIdx.x * 8;
    for (int i = tid; i < 8192; i += 256) Ws[i >> 6][i & 63] = W[i];
    const float* __restrict__ Y2 = Y + (size_t)n * 128;
    for (int i = tid; i < 1024; i += 256) {
        int r = i >> 7, c = i & 127;
        size_t gi = (size_t)(r0 + r) * 128 + c;
        Y1s[r][c] = Y[gi]; Y2s[r][c] = Y2[gi];
    }
    __syncthreads();
    const int c = tid & 127, rg = tid >> 7, d = c & 63, b64 = c & 64;
    const float bv = bias[d];
    for (int rr = rg; rr < 8; rr += 2) {
        float acc = bv;
#pragma unroll
        for (int k = 0; k < 64; k++) {
            acc = fmaf(Y1s[rr][b64 + k], Ws[k][d], acc);
            acc = fmaf(Y2s[rr][b64 + k], Ws[64 + k][d], acc);
        }
        float g = prev[(size_t)(r0 + rr) * 128 + c] + fmaxf(acc, 0.f);
        out[(size_t)(r0 + rr) * 128 + c] = g;
        oS[rr][c] = g;
    }
    __syncthreads();
    if (tid < 128) {
        float v[8];
#pragma unroll
        for (int j = 0; j < 8; j++) v[j] = oS[j][tid];
        *(uint4*)(Xf + (size_t)tid * n + r0) = pack8(v);
    }
}

// ===================== VNA epilogue (batched over 3 layers) =================
__global__ __launch_bounds__(256)
void epi_vna(const float* __restrict__ Y, const float* __restrict__ W,
             const float* __restrict__ bias, float* __restrict__ semb, int n)
{
    __shared__ float Ws[128][64];
    __shared__ float Y1s[8][128];
    __shared__ float Y2s[8][128];
    const int tid = threadIdx.x, r0 = blockIdx.x * 8, y = blockIdx.y;
    const float* __restrict__ Wp = W + y * 8192;
    const float* __restrict__ Y1 = Y + (size_t)(2 * y) * n * 128;
    const float* __restrict__ Y2 = Y1 + (size_t)n * 128;
    float* __restrict__ out = semb + (size_t)y * n * 128;
    for (int i = tid; i < 8192; i += 256) Ws[i >> 6][i & 63] = Wp[i];
    for (int i = tid; i < 1024; i += 256) {
        int r = i >> 7, c = i & 127;
        size_t gi = (size_t)(r0 + r) * 128 + c;
        Y1s[r][c] = Y1[gi]; Y2s[r][c] = Y2[gi];
    }
    __syncthreads();
    const int c = tid & 127, rg = tid >> 7, d = c & 63, b64 = c & 64;
    const float bv = bias[y * 64 + d];
    for (int rr = rg; rr < 8; rr += 2) {
        float acc = bv;
#pragma unroll
        for (int k = 0; k < 64; k++) {
            acc = fmaf(Y1s[rr][b64 + k], Ws[k][d], acc);
            acc = fmaf(Y2s[rr][b64 + k], Ws[64 + k][d], acc);
        }
        out[(size_t)(r0 + rr) * 128 + c] = fmaxf(acc, 0.f);
    }
}

// ===================== target epilogue + gated fusion (+X^T out) ============
#define SMEM_TGT 49152
__global__ __launch_bounds__(256)
void epi_tgt(const float* __restrict__ Y, const float* __restrict__ W,
             const float* __restrict__ bias, const float* __restrict__ S,
             const float* __restrict__ fWt, const float* __restrict__ fWs,
             const float* __restrict__ fb, float* __restrict__ xt,
             u16* __restrict__ Xf, int n)
{
    extern __shared__ __align__(16) char dsm[];
    float* Wbuf = (float*)dsm;                              // 32KB
    float (*Y1s)[128] = (float(*)[128])(dsm + 32768);
    float (*Y2s)[128] = (float(*)[128])(dsm + 36864);
    float (*tS)[128]  = (float(*)[128])(dsm + 40960);
    float (*sS)[128]  = (float(*)[128])(dsm + 45056);
    const int tid = threadIdx.x, r0 = blockIdx.x * 8;
    for (int i = tid; i < 8192; i += 256) Wbuf[i] = W[i];
    const float* __restrict__ Y2 = Y + (size_t)n * 128;
    for (int i = tid; i < 1024; i += 256) {
        int r = i >> 7, c = i & 127;
        size_t gi = (size_t)(r0 + r) * 128 + c;
        Y1s[r][c] = Y[gi]; Y2s[r][c] = Y2[gi];
        sS[r][c] = S[gi];
    }
    __syncthreads();
    const int c = tid & 127, rg = tid >> 7, d = c & 63, b64 = c & 64;
    const float bv = bias[d];
    for (int rr = rg; rr < 8; rr += 2) {
        float acc = bv;
#pragma unroll
        for (int k = 0; k < 64; k++) {
            acc = fmaf(Y1s[rr][b64 + k], Wbuf[k * 64 + d], acc);
            acc = fmaf(Y2s[rr][b64 + k], Wbuf[(64 + k) * 64 + d], acc);
        }
        tS[rr][c] = fmaxf(acc, 0.f);
    }
    __syncthreads();
    for (int i = tid; i < 4096; i += 256) { Wbuf[i] = fWt[i]; Wbuf[4096 + i] = fWs[i]; }
    __syncthreads();
    const float fbv = fb[d];
    for (int rr = rg; rr < 8; rr += 2) {
        float za = fbv;
#pragma unroll
        for (int k = 0; k < 64; k++) {
            za = fmaf(tS[rr][b64 + k], Wbuf[k * 64 + d], za);
            za = fmaf(sS[rr][b64 + k], Wbuf[4096 + k * 64 + d], za);
        }
        float z = 1.f / (1.f + expf(-za));
        float tv = tS[rr][c], sv = sS[rr][c];
        size_t gi = (size_t)(r0 + rr) * 128 + c;
        float nx = xt[gi] + z * tv + (1.f - z) * sv;
        xt[gi] = nx;
        Y1s[rr][c] = nx;   // transpose staging
    }
    __syncthreads();
    if (Xf && tid < 128) {
        float v[8];
#pragma unroll
        for (int j = 0; j < 8; j++) v[j] = Y1s[j][tid];
        *(uint4*)(Xf + (size_t)tid * n + r0) = pack8(v);
    }
}

// ===================== launcher =============================================
extern "C" void kernel_launch(void* const* d_in, const int* in_sizes, int n_in,
                              void* d_out, int out_size)
{
    (void)in_sizes; (void)n_in; (void)out_size;
    const float* A0      = (const float*)d_in[0];
    const float* A1      = (const float*)d_in[1];
    const float* A2      = (const float*)d_in[2];
    const float* x0      = (const float*)d_in[3];
    const float* x1      = (const float*)d_in[4];
    const float* src_nv1 = (const float*)d_in[5];
    const float* src_nv2 = (const float*)d_in[6];
    const float* src_W   = (const float*)d_in[7];
    const float* src_b   = (const float*)d_in[8];
    const float* vna_nv1 = (const float*)d_in[9];
    const float* vna_nv2 = (const float*)d_in[10];
    const float* vna_W   = (const float*)d_in[11];
    const float* vna_b   = (const float*)d_in[12];
    const float* tgt_nv1 = (const float*)d_in[13];
    const float* tgt_nv2 = (const float*)d_in[14];
    const float* tgt_W   = (const float*)d_in[15];
    const float* tgt_b   = (const float*)d_in[16];
    const float* fus_Wt  = (const float*)d_in[17];
    const float* fus_Ws  = (const float*)d_in[18];
    const float* fus_b   = (const float*)d_in[19];

    u16 *A0f, *A1f, *A2f, *Es, *Ev, *Et, *Xf;
    float *src_inv, *vna_inv, *tgt_inv, *lr, *semb, *Yb, *xtb;
    cudaGetSymbolAddress((void**)&A0f, g_A0f);
    cudaGetSymbolAddress((void**)&A1f, g_A1f);
    cudaGetSymbolAddress((void**)&A2f, g_A2f);
    cudaGetSymbolAddress((void**)&Es, g_Es);
    cudaGetSymbolAddress((void**)&Ev, g_Ev);
    cudaGetSymbolAddress((void**)&Et, g_Et);
    cudaGetSymbolAddress((void**)&Xf, g_Xf);
    cudaGetSymbolAddress((void**)&src_inv, g_src_inv);
    cudaGetSymbolAddress((void**)&vna_inv, g_vna_inv);
    cudaGetSymbolAddress((void**)&tgt_inv, g_tgt_inv);
    cudaGetSymbolAddress((void**)&lr, g_lr);
    cudaGetSymbolAddress((void**)&semb, g_semb);
    cudaGetSymbolAddress((void**)&Yb, g_Y);
    cudaGetSymbolAddress((void**)&xtb, g_xt);

    cudaFuncSetAttribute(hmma_gemm3, cudaFuncAttributeMaxDynamicSharedMemorySize, SMEM_GEMM);
    cudaFuncSetAttribute(epi_tgt, cudaFuncAttributeMaxDynamicSharedMemorySize, SMEM_TGT);
    cudaFuncSetAttribute(adp_fused, cudaFuncAttributeMaxDynamicSharedMemorySize, 8 * NS * 4);

    const size_t SLOT = (size_t)128 * NS;
    u16* Xf3 = Xf + 3 * SLOT;

    // packs + dense fp16 conversions
    pack_prep<<<NS / 8, 256>>>(x1, lr, Xf, NS);
    pack_prep<<<NT / 8, 256>>>(x0, xtb, Xf3, NT);
    tofp16_kernel<<<(NT * NT / 4 + 255) / 256, 256>>>(A0, A0f, NT * NT / 4);
    tofp16_kernel<<<(NT * NS / 4 + 255) / 256, 256>>>(A1, A1f, NT * NS / 4);
    tofp16_kernel<<<(NS * NS / 4 + 255) / 256, 256>>>(A2, A2f, NS * NS / 4);

    // adaptive adjacencies (single fused kernel each)
    adp_fused<<<NS / 8, 256, 8 * NS * 4>>>(src_nv1, src_nv2, Es, src_inv, NS);
    adp_fused<<<NT / 8, 256, 8 * NS * 4>>>(vna_nv1, vna_nv2, Ev, vna_inv, NS);
    adp_fused<<<NT / 8, 256, 8 * NT * 4>>>(tgt_nv1, tgt_nv2, Et, tgt_inv, NT);

    const int xS = ((NS + 63) / 64) * 2;   // 158
    const int xT = ((NT + 63) / 64) * 2;   // 126

    // ---- Source GC block (2 residual layers) ----
    for (int i = 0; i < 2; i++) {
        hmma_gemm3<<<dim3(xS, 1, 2), 128, SMEM_GEMM>>>(A2f, Es, src_inv,
            Xf + i * SLOT, Yb, NS, NS);
        epi_src<<<NS / 8, 256>>>(Yb, src_W + i * 8192, src_b + i * 64,
            lr + (size_t)i * NS * 128, lr + (size_t)(i + 1) * NS * 128,
            Xf + (i + 1) * SLOT, NS);
    }

    // ---- VNA block: 3 layers batched ----
    hmma_gemm3<<<dim3(xT, 3, 2), 128, SMEM_GEMM>>>(A1f, Ev, vna_inv, Xf, Yb, NT, NS);
    epi_vna<<<dim3(NT / 8, 3), 256>>>(Yb, vna_W, vna_b, semb, NT);

    // ---- Target GC block with gated fusion ----
    for (int i = 0; i < 3; i++) {
        hmma_gemm3<<<dim3(xT, 1, 2), 128, SMEM_GEMM>>>(A0f, Et, tgt_inv, Xf3, Yb, NT, NT);
        epi_tgt<<<NT / 8, 256, SMEM_TGT>>>(Yb, tgt_W + i * 8192, tgt_b + i * 64,
            semb + (size_t)i * NT * 128, fus_Wt + i * 4096, fus_Ws + i * 4096,
            fus_b + i * 64, xtb, (i < 2) ? Xf3 : (u16*)nullptr, NT);
    }

    unpack_kernel<<<(NT * 128 + 255) / 256, 256>>>(xtb, (float*)d_out, NT);
}

// round 8
// speedup vs baseline: 1.8697x; 1.0015x over previous
#include <cuda_runtime.h>
#include <cuda_fp16.h>
#include <math.h>
#include <stdint.h>

#define NT 4000
#define NS 5000
#define LOG2E 1.4426950408889634f

typedef unsigned short u16;

// ===================== scratch =============================================
__device__ __align__(16) u16 g_A0f[16000000];
__device__ __align__(16) u16 g_A1f[20000000];
__device__ __align__(16) u16 g_A2f[25000000];
__device__ __align__(16) u16 g_Es[25000000];
__device__ __align__(16) u16 g_Ev[20000000];
__device__ __align__(16) u16 g_Et[16000000];
__device__ __align__(16) u16 g_Xf[2432000];   // X^T fp16: slots 0-2 = lr (128*NS each), slot3 = xt (128*NT)
__device__ float g_src_inv[NS];
__device__ float g_vna_inv[NT];
__device__ float g_tgt_inv[NT];
__device__ __align__(16) float g_lr[3 * NS * 128];
__device__ __align__(16) float g_semb[3 * NT * 128];
__device__ __align__(16) float g_Y[3100000];
__device__ __align__(16) float g_xt[NT * 128];

// ===================== PTX helpers =========================================
__device__ __forceinline__ uint32_t smem_u32(const void* p) {
    uint32_t a;
    asm("{ .reg .u64 t; cvta.to.shared.u64 t, %1; cvt.u32.u64 %0, t; }" : "=r"(a) : "l"(p));
    return a;
}
#define CP_ASYNC16(saddr, gaddr, sz) \
    asm volatile("cp.async.ca.shared.global [%0], [%1], 16, %2;" :: "r"(saddr), "l"(gaddr), "r"(sz))
#define CP_COMMIT() asm volatile("cp.async.commit_group;" ::: "memory")
#define CP_WAIT1()  asm volatile("cp.async.wait_group 1;" ::: "memory")
#define LDSM4(r, a) \
    asm volatile("ldmatrix.sync.aligned.m8n8.x4.shared.b16 {%0,%1,%2,%3}, [%4];" \
        : "=r"((r)[0]), "=r"((r)[1]), "=r"((r)[2]), "=r"((r)[3]) : "r"(a))
#define MMA_FP16(c, A, b0, b1) \
    asm volatile("mma.sync.aligned.m16n8k16.row.col.f32.f16.f16.f32 " \
        "{%0,%1,%2,%3},{%4,%5,%6,%7},{%8,%9},{%0,%1,%2,%3};" \
        : "+f"((c)[0]), "+f"((c)[1]), "+f"((c)[2]), "+f"((c)[3]) \
        : "r"((A)[0]), "r"((A)[1]), "r"((A)[2]), "r"((A)[3]), "r"(b0), "r"(b1))

__device__ __forceinline__ uint32_t pack_h2(float a, float b) {
    return (uint32_t)__half_as_ushort(__float2half_rn(a)) |
           ((uint32_t)__half_as_ushort(__float2half_rn(b)) << 16);
}
__device__ __forceinline__ uint4 pack8(const float* v) {
    uint4 H;
    H.x = pack_h2(v[0], v[1]); H.y = pack_h2(v[2], v[3]);
    H.z = pack_h2(v[4], v[5]); H.w = pack_h2(v[6], v[7]);
    return H;
}

// ===================== small kernels ========================================
__global__ void unpack_kernel(const float* __restrict__ xp, float* __restrict__ out, int n) {
    int i = blockIdx.x * blockDim.x + threadIdx.x;
    if (i >= n * 128) return;
    int r = i >> 7, c = i & 127, b = c >> 6, d = c & 63;
    out[((size_t)b * n + r) * 64 + d] = xp[i];
}
__global__ void tofp16_kernel(const float* __restrict__ A, u16* __restrict__ F, int n4) {
    int i = blockIdx.x * blockDim.x + threadIdx.x;
    if (i >= n4) return;
    float4 v = ((const float4*)A)[i];
    uint2 o;
    o.x = pack_h2(v.x * 4096.f, v.y * 4096.f);
    o.y = pack_h2(v.z * 4096.f, v.w * 4096.f);
    ((uint2*)F)[i] = o;
}
// pack [B,n,64] -> [n,128] fp32 + transposed fp16 [128,n]
__global__ __launch_bounds__(256)
void pack_prep(const float* __restrict__ x, float* __restrict__ xp,
               u16* __restrict__ Xf, int n)
{
    __shared__ float t[8][128];
    const int tid = threadIdx.x, r0 = blockIdx.x * 8;
    for (int i = tid; i < 1024; i += 256) {
        int r = i >> 7, c = i & 127, b = c >> 6, d = c & 63;
        float v = x[((size_t)b * n + r0 + r) * 64 + d];
        xp[(size_t)(r0 + r) * 128 + c] = v;
        t[r][c] = v;
    }
    __syncthreads();
    if (tid < 128) {
        float v[8];
#pragma unroll
        for (int j = 0; j < 8; j++) v[j] = t[j][tid];
        *(uint4*)(Xf + (size_t)tid * n + r0) = pack8(v);
    }
}

// ===================== fused adaptive adjacency =============================
// One CTA = 8 rows. Dots buffered in dynamic smem; row max in-block;
// E = exp2f16x2((d-max)*log2e) fp16; inv = 1/rowsum (fp32, deterministic).
__global__ __launch_bounds__(256)
void adp_fused(const float* __restrict__ nv1, const float* __restrict__ nv2,
               u16* __restrict__ E, float* __restrict__ inv, int ncols)
{
    extern __shared__ float ds[];      // 8 * ncols floats
    __shared__ float v1s[8][30];
    __shared__ float red[8][8];
    __shared__ float Mrow[8];
    const int tid = threadIdx.x, r0 = blockIdx.x * 8;
    const int lane = tid & 31, wrp = tid >> 5;
    if (tid < 240) v1s[tid / 30][tid % 30] = nv1[(size_t)(r0 + tid / 30) * 30 + tid % 30];
    __syncthreads();

    float mx[8];
#pragma unroll
    for (int r = 0; r < 8; r++) mx[r] = 0.f;
    for (int c = tid; c < ncols; c += 256) {
        float col[30];
#pragma unroll
        for (int q = 0; q < 30; q++) col[q] = nv2[(size_t)q * ncols + c];
#pragma unroll
        for (int r = 0; r < 8; r++) {
            float dot = 0.f;
#pragma unroll
            for (int q = 0; q < 30; q++) dot = fmaf(v1s[r][q], col[q], dot);
            float dp = fmaxf(dot, 0.f);
            ds[r * ncols + c] = dp;
            mx[r] = fmaxf(mx[r], dp);
        }
    }
#pragma unroll
    for (int r = 0; r < 8; r++) {
        float v = mx[r];
#pragma unroll
        for (int off = 16; off > 0; off >>= 1)
            v = fmaxf(v, __shfl_down_sync(0xffffffffu, v, off));
        if (lane == 0) red[wrp][r] = v;
    }
    __syncthreads();
    if (tid < 8) {
        float v = red[0][tid];
#pragma unroll
        for (int w = 1; w < 8; w++) v = fmaxf(v, red[w][tid]);
        Mrow[tid] = v;
    }
    __syncthreads();

    float M[8], ps[8];
#pragma unroll
    for (int r = 0; r < 8; r++) { M[r] = Mrow[r]; ps[r] = 0.f; }
    for (int c = tid * 2; c < ncols; c += 512) {
#pragma unroll
        for (int r = 0; r < 8; r++) {
            size_t idx = (size_t)(r0 + r) * ncols + c;
            float t0 = (ds[r * ncols + c]     - M[r]) * LOG2E;
            float t1 = (ds[r * ncols + c + 1] - M[r]) * LOG2E;
            __half2 tin = __floats2half2_rn(t0, t1);
            uint32_t ti = *(uint32_t*)&tin, eo;
            asm("ex2.approx.f16x2 %0, %1;" : "=r"(eo) : "r"(ti));
            *(uint32_t*)(E + idx) = eo;
            float2 ef = __half22float2(*(__half2*)&eo);
            ps[r] += ef.x + ef.y;
        }
    }
#pragma unroll
    for (int r = 0; r < 8; r++) {
        float v = ps[r];
#pragma unroll
        for (int off = 16; off > 0; off >>= 1) v += __shfl_down_sync(0xffffffffu, v, off);
        if (lane == 0) red[wrp][r] = v;
    }
    __syncthreads();
    if (tid < 8) {
        float s = 0.f;
#pragma unroll
        for (int w = 0; w < 8; w++) s += red[w][tid];
        inv[r0 + tid] = 1.0f / s;
    }
}

// ===================== fp16 single-pass HMMA GEMM ===========================
// 64x64 tile, 128 threads (4 warps 2x2, warp tile 32x32), KT=64, double-buffered.
// grid: x = rowtiles*2 (bit0 = N-half), y = X slot, z = support (0 dense, 1 adaptive)
#define GKT 64
#define STAGE_B 16384   // A 8K | B 8K
#define SMEM_GEMM (2 * STAGE_B)

__device__ __forceinline__ void stage_load3(
    uint32_t sdst, const u16* __restrict__ Ag, const u16* __restrict__ Bg,
    int row0, int kbase, int n, int m, int tid)
{
#pragma unroll
    for (int t = 0; t < 4; t++) {
        int id = tid + t * 128;
        int r = id >> 3, kc = id & 7;
        int gr = row0 + r, gk = kbase + kc * 8;
        bool v = (gr < n) && (gk < m);
        size_t gi = (size_t)(v ? gr : 0) * m + (v ? gk : 0);
        uint32_t off = r * 128 + kc * 16;
        uint32_t sw = off ^ ((off >> 3) & 0x70);
        CP_ASYNC16(sdst + sw, Ag + gi, v ? 16u : 0u);
    }
#pragma unroll
    for (int t = 0; t < 4; t++) {
        int id = tid + t * 128;
        int r = id >> 3, kc = id & 7;
        int gk = kbase + kc * 8;
        bool v = (gk < m);
        size_t gi = (size_t)r * m + (v ? gk : 0);
        uint32_t off = r * 128 + kc * 16;
        uint32_t sw = off ^ ((off >> 3) & 0x70);
        CP_ASYNC16(sdst + 8192 + sw, Bg + gi, v ? 16u : 0u);
    }
}

__global__ __launch_bounds__(128, 4)
void hmma_gemm3(const u16* __restrict__ Af, const u16* __restrict__ Ef,
                const float* __restrict__ invsum,
                const u16* __restrict__ Xf,
                float* __restrict__ Y, int n, int m)
{
    extern __shared__ __align__(128) char smem[];
    const uint32_t sb = smem_u32(smem);
    const int tid = threadIdx.x, lane = tid & 31, wid = tid >> 5;
    const int wm = wid >> 1, wn = wid & 1;
    const int tile = blockIdx.x >> 1, nh = blockIdx.x & 1;
    const int row0 = tile * 64, col0 = nh * 64;
    const u16* __restrict__ A = blockIdx.z ? Ef : Af;
    const u16* __restrict__ B = Xf + ((size_t)blockIdx.y * 128 + col0) * m;
    const int ktn = (m + GKT - 1) / GKT;

    float acc[2][4][4];
#pragma unroll
    for (int i = 0; i < 2; i++)
#pragma unroll
        for (int j = 0; j < 4; j++)
#pragma unroll
            for (int q = 0; q < 4; q++) acc[i][j][q] = 0.f;

    uint32_t arow[2], axor[2];
#pragma unroll
    for (int mt = 0; mt < 2; mt++) {
        int r = wm * 32 + mt * 16 + (lane & 7) + (((lane >> 3) & 1) << 3);
        arow[mt] = (uint32_t)r * 128;
        axor[mt] = ((uint32_t)r * 16) & 0x70;
    }
    const uint32_t akbs = ((lane >> 4) & 1) * 16;
    uint32_t brow[2], bxor[2];
#pragma unroll
    for (int bt = 0; bt < 2; bt++) {
        int r = wn * 32 + bt * 16 + (lane & 7) + (((lane >> 4) & 1) << 3);
        brow[bt] = (uint32_t)r * 128;
        bxor[bt] = ((uint32_t)r * 16) & 0x70;
    }
    const uint32_t bkbs = ((lane >> 3) & 1) * 16;

    stage_load3(sb, A, B, row0, 0, n, m, tid);
    CP_COMMIT();

    for (int kt = 0; kt < ktn; kt++) {
        if (kt + 1 < ktn)
            stage_load3(sb + ((kt + 1) & 1) * STAGE_B, A, B, row0, (kt + 1) * GKT, n, m, tid);
        CP_COMMIT();
        CP_WAIT1();
        __syncthreads();
        const uint32_t stb = sb + (kt & 1) * STAGE_B;
#pragma unroll
        for (int ks = 0; ks < 4; ks++) {
            const uint32_t kb = ks * 32;
            uint32_t fa[2][4], fb[2][4];
#pragma unroll
            for (int mt = 0; mt < 2; mt++)
                LDSM4(fa[mt], stb + arow[mt] + ((kb + akbs) ^ axor[mt]));
#pragma unroll
            for (int bt = 0; bt < 2; bt++)
                LDSM4(fb[bt], stb + 8192 + brow[bt] + ((kb + bkbs) ^ bxor[bt]));
#pragma unroll
            for (int mt = 0; mt < 2; mt++)
#pragma unroll
                for (int nt = 0; nt < 4; nt++) {
                    const int g = nt >> 1, h = (nt & 1) << 1;
                    MMA_FP16(acc[mt][nt], fa[mt], fb[g][h], fb[g][h + 1]);
                }
        }
        __syncthreads();
    }

    float* __restrict__ Yz = Y + (size_t)(blockIdx.y * 2 + blockIdx.z) * n * 128;
#pragma unroll
    for (int mt = 0; mt < 2; mt++) {
        int gr0 = row0 + wm * 32 + mt * 16 + (lane >> 2);
        int gr1 = gr0 + 8;
        float s0, s1;
        if (blockIdx.z) {
            s0 = (gr0 < n) ? invsum[gr0] : 0.f;
            s1 = (gr1 < n) ? invsum[gr1] : 0.f;
        } else {
            s0 = s1 = 2.44140625e-4f;  // 1/4096
        }
#pragma unroll
        for (int nt = 0; nt < 4; nt++) {
            int col = col0 + wn * 32 + nt * 8 + ((lane & 3) << 1);
            if (gr0 < n)
                *(float2*)(Yz + (size_t)gr0 * 128 + col) =
                    make_float2(acc[mt][nt][0] * s0, acc[mt][nt][1] * s0);
            if (gr1 < n)
                *(float2*)(Yz + (size_t)gr1 * 128 + col) =
                    make_float2(acc[mt][nt][2] * s1, acc[mt][nt][3] * s1);
        }
    }
}

// ===================== source epilogue (+residual, +X^T fp16 out) ===========
__global__ __launch_bounds__(256)
void epi_src(const float* __restrict__ Y, const float* __restrict__ W,
             const float* __restrict__ bias, const float* __restrict__ prev,
             float* __restrict__ out, u16* __restrict__ Xf, int n)
{
    __shared__ float Ws[128][64];
    __shared__ float Y1s[8][128];
    __shared__ float Y2s[8][128];
    __shared__ float oS[8][128];
    const int tid = threadIdx.x, r0 = blockIdx.x * 8;
    for (int i = tid; i < 8192; i += 256) Ws[i >> 6][i & 63] = W[i];
    const float* __restrict__ Y2 = Y + (size_t)n * 128;
    for (int i = tid; i < 1024; i += 256) {
        int r = i >> 7, c = i & 127;
        size_t gi = (size_t)(r0 + r) * 128 + c;
        Y1s[r][c] = Y[gi]; Y2s[r][c] = Y2[gi];
    }
    __syncthreads();
    const int c = tid & 127, rg = tid >> 7, d = c & 63, b64 = c & 64;
    const float bv = bias[d];
    for (int rr = rg; rr < 8; rr += 2) {
        float acc = bv;
#pragma unroll
        for (int k = 0; k < 64; k++) {
            acc = fmaf(Y1s[rr][b64 + k], Ws[k][d], acc);
            acc = fmaf(Y2s[rr][b64 + k], Ws[64 + k][d], acc);
        }
        float g = prev[(size_t)(r0 + rr) * 128 + c] + fmaxf(acc, 0.f);
        out[(size_t)(r0 + rr) * 128 + c] = g;
        oS[rr][c] = g;
    }
    __syncthreads();
    if (tid < 128) {
        float v[8];
#pragma unroll
        for (int j = 0; j < 8; j++) v[j] = oS[j][tid];
        *(uint4*)(Xf + (size_t)tid * n + r0) = pack8(v);
    }
}

// ===================== VNA epilogue (batched over 3 layers) =================
__global__ __launch_bounds__(256)
void epi_vna(const float* __restrict__ Y, const float* __restrict__ W,
             const float* __restrict__ bias, float* __restrict__ semb, int n)
{
    __shared__ float Ws[128][64];
    __shared__ float Y1s[8][128];
    __shared__ float Y2s[8][128];
    const int tid = threadIdx.x, r0 = blockIdx.x * 8, y = blockIdx.y;
    const float* __restrict__ Wp = W + y * 8192;
    const float* __restrict__ Y1 = Y + (size_t)(2 * y) * n * 128;
    const float* __restrict__ Y2 = Y1 + (size_t)n * 128;
    float* __restrict__ out = semb + (size_t)y * n * 128;
    for (int i = tid; i < 8192; i += 256) Ws[i >> 6][i & 63] = Wp[i];
    for (int i = tid; i < 1024; i += 256) {
        int r = i >> 7, c = i & 127;
        size_t gi = (size_t)(r0 + r) * 128 + c;
        Y1s[r][c] = Y1[gi]; Y2s[r][c] = Y2[gi];
    }
    __syncthreads();
    const int c = tid & 127, rg = tid >> 7, d = c & 63, b64 = c & 64;
    const float bv = bias[y * 64 + d];
    for (int rr = rg; rr < 8; rr += 2) {
        float acc = bv;
#pragma unroll
        for (int k = 0; k < 64; k++) {
            acc = fmaf(Y1s[rr][b64 + k], Ws[k][d], acc);
            acc = fmaf(Y2s[rr][b64 + k], Ws[64 + k][d], acc);
        }
        out[(size_t)(r0 + rr) * 128 + c] = fmaxf(acc, 0.f);
    }
}

// ===================== target epilogue + gated fusion (+X^T out) ============
#define SMEM_TGT 49152
__global__ __launch_bounds__(256)
void epi_tgt(const float* __restrict__ Y, const float* __restrict__ W,
             const float* __restrict__ bias, const float* __restrict__ S,
             const float* __restrict__ fWt, const float* __restrict__ fWs,
             const float* __restrict__ fb, float* __restrict__ xt,
             u16* __restrict__ Xf, int n)
{
    extern __shared__ __align__(16) char dsm[];
    float* Wbuf = (float*)dsm;                              // 32KB
    float (*Y1s)[128] = (float(*)[128])(dsm + 32768);
    float (*Y2s)[128] = (float(*)[128])(dsm + 36864);
    float (*tS)[128]  = (float(*)[128])(dsm + 40960);
    float (*sS)[128]  = (float(*)[128])(dsm + 45056);
    const int tid = threadIdx.x, r0 = blockIdx.x * 8;
    for (int i = tid; i < 8192; i += 256) Wbuf[i] = W[i];
    const float* __restrict__ Y2 = Y + (size_t)n * 128;
    for (int i = tid; i < 1024; i += 256) {
        int r = i >> 7, c = i & 127;
        size_t gi = (size_t)(r0 + r) * 128 + c;
        Y1s[r][c] = Y[gi]; Y2s[r][c] = Y2[gi];
        sS[r][c] = S[gi];
    }
    __syncthreads();
    const int c = tid & 127, rg = tid >> 7, d = c & 63, b64 = c & 64;
    const float bv = bias[d];
    for (int rr = rg; rr < 8; rr += 2) {
        float acc = bv;
#pragma unroll
        for (int k = 0; k < 64; k++) {
            acc = fmaf(Y1s[rr][b64 + k], Wbuf[k * 64 + d], acc);
            acc = fmaf(Y2s[rr][b64 + k], Wbuf[(64 + k) * 64 + d], acc);
        }
        tS[rr][c] = fmaxf(acc, 0.f);
    }
    __syncthreads();
    for (int i = tid; i < 4096; i += 256) { Wbuf[i] = fWt[i]; Wbuf[4096 + i] = fWs[i]; }
    __syncthreads();
    const float fbv = fb[d];
    for (int rr = rg; rr < 8; rr += 2) {
        float za = fbv;
#pragma unroll
        for (int k = 0; k < 64; k++) {
            za = fmaf(tS[rr][b64 + k], Wbuf[k * 64 + d], za);
            za = fmaf(sS[rr][b64 + k], Wbuf[4096 + k * 64 + d], za);
        }
        float z = 1.f / (1.f + expf(-za));
        float tv = tS[rr][c], sv = sS[rr][c];
        size_t gi = (size_t)(r0 + rr) * 128 + c;
        float nx = xt[gi] + z * tv + (1.f - z) * sv;
        xt[gi] = nx;
        Y1s[rr][c] = nx;   // transpose staging
    }
    __syncthreads();
    if (Xf && tid < 128) {
        float v[8];
#pragma unroll
        for (int j = 0; j < 8; j++) v[j] = Y1s[j][tid];
        *(uint4*)(Xf + (size_t)tid * n + r0) = pack8(v);
    }
}

// ===================== launcher =============================================
extern "C" void kernel_launch(void* const* d_in, const int* in_sizes, int n_in,
                              void* d_out, int out_size)
{
    (void)in_sizes; (void)n_in; (void)out_size;
    const float* A0      = (const float*)d_in[0];
    const float* A1      = (const float*)d_in[1];
    const float* A2      = (const float*)d_in[2];
    const float* x0      = (const float*)d_in[3];
    const float* x1      = (const float*)d_in[4];
    const float* src_nv1 = (const float*)d_in[5];
    const float* src_nv2 = (const float*)d_in[6];
    const float* src_W   = (const float*)d_in[7];
    const float* src_b   = (const float*)d_in[8];
    const float* vna_nv1 = (const float*)d_in[9];
    const float* vna_nv2 = (const float*)d_in[10];
    const float* vna_W   = (const float*)d_in[11];
    const float* vna_b   = (const float*)d_in[12];
    const float* tgt_nv1 = (const float*)d_in[13];
    const float* tgt_nv2 = (const float*)d_in[14];
    const float* tgt_W   = (const float*)d_in[15];
    const float* tgt_b   = (const float*)d_in[16];
    const float* fus_Wt  = (const float*)d_in[17];
    const float* fus_Ws  = (const float*)d_in[18];
    const float* fus_b   = (const float*)d_in[19];

    u16 *A0f, *A1f, *A2f, *Es, *Ev, *Et, *Xf;
    float *src_inv, *vna_inv, *tgt_inv, *lr, *semb, *Yb, *xtb;
    cudaGetSymbolAddress((void**)&A0f, g_A0f);
    cudaGetSymbolAddress((void**)&A1f, g_A1f);
    cudaGetSymbolAddress((void**)&A2f, g_A2f);
    cudaGetSymbolAddress((void**)&Es, g_Es);
    cudaGetSymbolAddress((void**)&Ev, g_Ev);
    cudaGetSymbolAddress((void**)&Et, g_Et);
    cudaGetSymbolAddress((void**)&Xf, g_Xf);
    cudaGetSymbolAddress((void**)&src_inv, g_src_inv);
    cudaGetSymbolAddress((void**)&vna_inv, g_vna_inv);
    cudaGetSymbolAddress((void**)&tgt_inv, g_tgt_inv);
    cudaGetSymbolAddress((void**)&lr, g_lr);
    cudaGetSymbolAddress((void**)&semb, g_semb);
    cudaGetSymbolAddress((void**)&Yb, g_Y);
    cudaGetSymbolAddress((void**)&xtb, g_xt);

    cudaFuncSetAttribute(hmma_gemm3, cudaFuncAttributeMaxDynamicSharedMemorySize, SMEM_GEMM);
    cudaFuncSetAttribute(epi_tgt, cudaFuncAttributeMaxDynamicSharedMemorySize, SMEM_TGT);
    cudaFuncSetAttribute(adp_fused, cudaFuncAttributeMaxDynamicSharedMemorySize, 8 * NS * 4);

    const size_t SLOT = (size_t)128 * NS;
    u16* Xf3 = Xf + 3 * SLOT;

    // packs + dense fp16 conversions
    pack_prep<<<NS / 8, 256>>>(x1, lr, Xf, NS);
    pack_prep<<<NT / 8, 256>>>(x0, xtb, Xf3, NT);
    tofp16_kernel<<<(NT * NT / 4 + 255) / 256, 256>>>(A0, A0f, NT * NT / 4);
    tofp16_kernel<<<(NT * NS / 4 + 255) / 256, 256>>>(A1, A1f, NT * NS / 4);
    tofp16_kernel<<<(NS * NS / 4 + 255) / 256, 256>>>(A2, A2f, NS * NS / 4);

    // adaptive adjacencies (single fused kernel each)
    adp_fused<<<NS / 8, 256, 8 * NS * 4>>>(src_nv1, src_nv2, Es, src_inv, NS);
    adp_fused<<<NT / 8, 256, 8 * NS * 4>>>(vna_nv1, vna_nv2, Ev, vna_inv, NS);
    adp_fused<<<NT / 8, 256, 8 * NT * 4>>>(tgt_nv1, tgt_nv2, Et, tgt_inv, NT);

    const int xS = ((NS + 63) / 64) * 2;   // 158
    const int xT = ((NT + 63) / 64) * 2;   // 126

    // ---- Source GC block (2 residual layers) ----
    for (int i = 0; i < 2; i++) {
        hmma_gemm3<<<dim3(xS, 1, 2), 128, SMEM_GEMM>>>(A2f, Es, src_inv,
            Xf + i * SLOT, Yb, NS, NS);
        epi_src<<<NS / 8, 256>>>(Yb, src_W + i * 8192, src_b + i * 64,
            lr + (size_t)i * NS * 128, lr + (size_t)(i + 1) * NS * 128,
            Xf + (i + 1) * SLOT, NS);
    }

    // ---- VNA block: 3 layers batched ----
    hmma_gemm3<<<dim3(xT, 3, 2), 128, SMEM_GEMM>>>(A1f, Ev, vna_inv, Xf, Yb, NT, NS);
    epi_vna<<<dim3(NT / 8, 3), 256>>>(Yb, vna_W, vna_b, semb, NT);

    // ---- Target GC block with gated fusion ----
    for (int i = 0; i < 3; i++) {
        hmma_gemm3<<<dim3(xT, 1, 2), 128, SMEM_GEMM>>>(A0f, Et, tgt_inv, Xf3, Yb, NT, NT);
        epi_tgt<<<NT / 8, 256, SMEM_TGT>>>(Yb, tgt_W + i * 8192, tgt_b + i * 64,
            semb + (size_t)i * NT * 128, fus_Wt + i * 4096, fus_Ws + i * 4096,
            fus_b + i * 64, xtb, (i < 2) ? Xf3 : (u16*)nullptr, NT);
    }

    unpack_kernel<<<(NT * 128 + 255) / 256, 256>>>(xtb, (float*)d_out, NT);
}

// round 9
// speedup vs baseline: 2.0884x; 1.1170x over previous
#include <cuda_runtime.h>
#include <cuda_fp16.h>
#include <math.h>
#include <stdint.h>

#define NT 4000
#define NS 5000
#define LOG2E 1.4426950408889634f
typedef unsigned short u16;

// ===================== scratch =============================================
__device__ __align__(16) u16 g_A0f[16000000];
__device__ __align__(16) u16 g_A1f[20000000];
__device__ __align__(16) u16 g_A2f[25000000];
__device__ __align__(16) u16 g_Es[25000000];
__device__ __align__(16) u16 g_Ev[20000000];
__device__ __align__(16) u16 g_Et[16000000];
__device__ __align__(16) u16 g_Xf[2432000];
__device__ float g_src_inv[NS];
__device__ float g_vna_inv[NT];
__device__ float g_tgt_inv[NT];
__device__ __align__(16) float g_lr[3 * NS * 128];
__device__ __align__(16) float g_semb[3 * NT * 128];
__device__ __align__(16) float g_Y[3100000];
__device__ __align__(16) float g_xt[NT * 128];

// ===================== PTX helpers =========================================
__device__ __forceinline__ uint32_t smem_u32(const void* p) {
    uint32_t a;
    asm("{ .reg .u64 t; cvta.to.shared.u64 t, %1; cvt.u32.u64 %0, t; }" : "=r"(a) : "l"(p));
    return a;
}
#define CP_ASYNC16(saddr, gaddr, sz) \
    asm volatile("cp.async.ca.shared.global [%0], [%1], 16, %2;" :: "r"(saddr), "l"(gaddr), "r"(sz))
#define CP_COMMIT() asm volatile("cp.async.commit_group;" ::: "memory")
#define CP_WAIT1()  asm volatile("cp.async.wait_group 1;" ::: "memory")
#define LDSM4(r, a) \
    asm volatile("ldmatrix.sync.aligned.m8n8.x4.shared.b16 {%0,%1,%2,%3}, [%4];" \
        : "=r"((r)[0]), "=r"((r)[1]), "=r"((r)[2]), "=r"((r)[3]) : "r"(a))
#define MMA_FP16(c, A, b0, b1) \
    asm volatile("mma.sync.aligned.m16n8k16.row.col.f32.f16.f16.f32 " \
        "{%0,%1,%2,%3},{%4,%5,%6,%7},{%8,%9},{%0,%1,%2,%3};" \
        : "+f"((c)[0]), "+f"((c)[1]), "+f"((c)[2]), "+f"((c)[3]) \
        : "r"((A)[0]), "r"((A)[1]), "r"((A)[2]), "r"((A)[3]), "r"(b0), "r"(b1))

__device__ __forceinline__ uint32_t pack_h2(float a, float b) {
    return (uint32_t)__half_as_ushort(__float2half_rn(a)) |
           ((uint32_t)__half_as_ushort(__float2half_rn(b)) << 16);
}
__device__ __forceinline__ uint4 pack8(const float* v) {
    uint4 H;
    H.x = pack_h2(v[0], v[1]); H.y = pack_h2(v[2], v[3]);
    H.z = pack_h2(v[4], v[5]); H.w = pack_h2(v[6], v[7]);
    return H;
}
__device__ __forceinline__ uint32_t swz(uint32_t x) { return x ^ ((x >> 3) & 0x70); }

// ===================== small kernels ========================================
__global__ void unpack_kernel(const float* __restrict__ xp, float* __restrict__ out, int n) {
    int i = blockIdx.x * blockDim.x + threadIdx.x;
    if (i >= n * 128) return;
    int r = i >> 7, c = i & 127, b = c >> 6, d = c & 63;
    out[((size_t)b * n + r) * 64 + d] = xp[i];
}
__global__ void tofp16_kernel(const float* __restrict__ A, u16* __restrict__ F, int n4) {
    int i = blockIdx.x * blockDim.x + threadIdx.x;
    if (i >= n4) return;
    float4 v = ((const float4*)A)[i];
    uint2 o;
    o.x = pack_h2(v.x * 4096.f, v.y * 4096.f);
    o.y = pack_h2(v.z * 4096.f, v.w * 4096.f);
    ((uint2*)F)[i] = o;
}
__global__ __launch_bounds__(256)
void pack_prep(const float* __restrict__ x, float* __restrict__ xp,
               u16* __restrict__ Xf, int n)
{
    __shared__ float t[8][128];
    const int tid = threadIdx.x, r0 = blockIdx.x * 8;
    for (int i = tid; i < 1024; i += 256) {
        int r = i >> 7, c = i & 127, b = c >> 6, d = c & 63;
        float v = x[((size_t)b * n + r0 + r) * 64 + d];
        xp[(size_t)(r0 + r) * 128 + c] = v;
        t[r][c] = v;
    }
    __syncthreads();
    if (tid < 128) {
        float v[8];
#pragma unroll
        for (int j = 0; j < 8; j++) v[j] = t[j][tid];
        *(uint4*)(Xf + (size_t)tid * n + r0) = pack8(v);
    }
}

// ===================== fused adaptive adjacency (4 rows/CTA, occ 2) =========
__global__ __launch_bounds__(256)
void adp_fused(const float* __restrict__ nv1, const float* __restrict__ nv2,
               u16* __restrict__ E, float* __restrict__ inv, int ncols)
{
    extern __shared__ float ds[];      // 4 * ncols
    __shared__ float v1s[4][30];
    __shared__ float red[8][4];
    __shared__ float Mrow[4];
    const int tid = threadIdx.x, r0 = blockIdx.x * 4;
    const int lane = tid & 31, wrp = tid >> 5;
    if (tid < 120) v1s[tid / 30][tid % 30] = nv1[(size_t)(r0 + tid / 30) * 30 + tid % 30];
    __syncthreads();

    float mx[4];
#pragma unroll
    for (int r = 0; r < 4; r++) mx[r] = 0.f;
    for (int c = tid; c < ncols; c += 256) {
        float col[30];
#pragma unroll
        for (int q = 0; q < 30; q++) col[q] = nv2[(size_t)q * ncols + c];
#pragma unroll
        for (int r = 0; r < 4; r++) {
            float dot = 0.f;
#pragma unroll
            for (int q = 0; q < 30; q++) dot = fmaf(v1s[r][q], col[q], dot);
            float dp = fmaxf(dot, 0.f);
            ds[r * ncols + c] = dp;
            mx[r] = fmaxf(mx[r], dp);
        }
    }
#pragma unroll
    for (int r = 0; r < 4; r++) {
        float v = mx[r];
#pragma unroll
        for (int off = 16; off > 0; off >>= 1)
            v = fmaxf(v, __shfl_down_sync(0xffffffffu, v, off));
        if (lane == 0) red[wrp][r] = v;
    }
    __syncthreads();
    if (tid < 4) {
        float v = red[0][tid];
#pragma unroll
        for (int w = 1; w < 8; w++) v = fmaxf(v, red[w][tid]);
        Mrow[tid] = v;
    }
    __syncthreads();

    float M[4], ps[4];
#pragma unroll
    for (int r = 0; r < 4; r++) { M[r] = Mrow[r]; ps[r] = 0.f; }
    for (int c = tid * 2; c < ncols; c += 512) {
#pragma unroll
        for (int r = 0; r < 4; r++) {
            size_t idx = (size_t)(r0 + r) * ncols + c;
            float t0 = (ds[r * ncols + c]     - M[r]) * LOG2E;
            float t1 = (ds[r * ncols + c + 1] - M[r]) * LOG2E;
            __half2 tin = __floats2half2_rn(t0, t1);
            uint32_t ti = *(uint32_t*)&tin, eo;
            asm("ex2.approx.f16x2 %0, %1;" : "=r"(eo) : "r"(ti));
            *(uint32_t*)(E + idx) = eo;
            float2 ef = __half22float2(*(__half2*)&eo);
            ps[r] += ef.x + ef.y;
        }
    }
#pragma unroll
    for (int r = 0; r < 4; r++) {
        float v = ps[r];
#pragma unroll
        for (int off = 16; off > 0; off >>= 1) v += __shfl_down_sync(0xffffffffu, v, off);
        if (lane == 0) red[wrp][r] = v;
    }
    __syncthreads();
    if (tid < 4) {
        float s = 0.f;
#pragma unroll
        for (int w = 0; w < 8; w++) s += red[w][tid];
        inv[r0 + tid] = 1.0f / s;
    }
}

// ===================== merged-support HMMA GEMM =============================
// CTA = 32 rows x 64 cols, BOTH supports (B loaded once). 128 thr, warp 16x32.
// grid: x = rowtiles*2 (bit0 = col half), y = X slot.
#define GKT 64
#define STAGE_B 16384   // Ad 4K | Ae 4K | B 8K
#define SMEM_GEMM (2 * STAGE_B)

__device__ __forceinline__ void stage_ldm(uint32_t sdst,
    const u16* __restrict__ Ad, const u16* __restrict__ Ae, const u16* __restrict__ B,
    int row0, int kbase, int n, int m, int tid)
{
#pragma unroll
    for (int t = 0; t < 2; t++) {
        int id = tid + t * 128;
        int r = id >> 3, kc = id & 7;
        int gr = row0 + r, gk = kbase + kc * 8;
        bool v = (gr < n) && (gk < m);
        size_t gi = (size_t)(v ? gr : 0) * m + (v ? gk : 0);
        uint32_t sw = swz(r * 128 + kc * 16);
        unsigned sz = v ? 16u : 0u;
        CP_ASYNC16(sdst + sw, Ad + gi, sz);
        CP_ASYNC16(sdst + 4096 + sw, Ae + gi, sz);
    }
#pragma unroll
    for (int t = 0; t < 4; t++) {
        int id = tid + t * 128;
        int cr = id >> 3, kc = id & 7;
        int gk = kbase + kc * 8;
        bool v = (gk < m);
        size_t gi = (size_t)cr * m + (v ? gk : 0);
        uint32_t sw = swz(cr * 128 + kc * 16);
        CP_ASYNC16(sdst + 8192 + sw, B + gi, v ? 16u : 0u);
    }
}

__global__ __launch_bounds__(128, 4)
void hmma_gemm3m(const u16* __restrict__ Af, const u16* __restrict__ Ef,
                 const float* __restrict__ invsum,
                 const u16* __restrict__ Xf,
                 float* __restrict__ Y, int n, int m)
{
    extern __shared__ __align__(128) char smem[];
    const uint32_t sb = smem_u32(smem);
    const int tid = threadIdx.x, lane = tid & 31, wid = tid >> 5;
    const int wm = wid >> 1, wn = wid & 1;
    const int tile = blockIdx.x >> 1, nh = blockIdx.x & 1;
    const int row0 = tile * 32, col0 = nh * 64;
    const u16* __restrict__ B = Xf + ((size_t)blockIdx.y * 128 + col0) * m;
    const int ktn = (m + GKT - 1) / GKT;

    float accD[4][4], accE[4][4];
#pragma unroll
    for (int j = 0; j < 4; j++)
#pragma unroll
        for (int q = 0; q < 4; q++) { accD[j][q] = 0.f; accE[j][q] = 0.f; }

    uint32_t arow, axor;
    { int r = wm * 16 + (lane & 7) + (((lane >> 3) & 1) << 3);
      arow = (uint32_t)r * 128; axor = ((uint32_t)r * 16) & 0x70; }
    const uint32_t akbs = ((lane >> 4) & 1) * 16;
    uint32_t brow[2], bxor[2];
#pragma unroll
    for (int bt = 0; bt < 2; bt++) {
        int r = wn * 32 + bt * 16 + (lane & 7) + (((lane >> 4) & 1) << 3);
        brow[bt] = (uint32_t)r * 128; bxor[bt] = ((uint32_t)r * 16) & 0x70;
    }
    const uint32_t bkbs = ((lane >> 3) & 1) * 16;

    stage_ldm(sb, Af, Ef, B, row0, 0, n, m, tid);
    CP_COMMIT();

    for (int kt = 0; kt < ktn; kt++) {
        if (kt + 1 < ktn)
            stage_ldm(sb + ((kt + 1) & 1) * STAGE_B, Af, Ef, B, row0, (kt + 1) * GKT, n, m, tid);
        CP_COMMIT();
        CP_WAIT1();
        __syncthreads();
        const uint32_t stb = sb + (kt & 1) * STAGE_B;
#pragma unroll
        for (int ks = 0; ks < 4; ks++) {
            const uint32_t kb = ks * 32;
            uint32_t fad[4], fae[4], fb[2][4];
            LDSM4(fad, stb + arow + ((kb + akbs) ^ axor));
            LDSM4(fae, stb + 4096 + arow + ((kb + akbs) ^ axor));
#pragma unroll
            for (int bt = 0; bt < 2; bt++)
                LDSM4(fb[bt], stb + 8192 + brow[bt] + ((kb + bkbs) ^ bxor[bt]));
#pragma unroll
            for (int nt = 0; nt < 4; nt++) {
                const int g = nt >> 1, h = (nt & 1) << 1;
                MMA_FP16(accD[nt], fad, fb[g][h], fb[g][h + 1]);
                MMA_FP16(accE[nt], fae, fb[g][h], fb[g][h + 1]);
            }
        }
        __syncthreads();
    }

    float* __restrict__ Yd = Y + (size_t)(blockIdx.y * 2) * n * 128;
    float* __restrict__ Ye = Yd + (size_t)n * 128;
    const int gr0 = row0 + wm * 16 + (lane >> 2), gr1 = gr0 + 8;
    const float SD = 2.44140625e-4f;   // 1/4096 dense prescale undo
    const float e0 = (gr0 < n) ? invsum[gr0] : 0.f;
    const float e1 = (gr1 < n) ? invsum[gr1] : 0.f;
#pragma unroll
    for (int nt = 0; nt < 4; nt++) {
        int col = col0 + wn * 32 + nt * 8 + ((lane & 3) << 1);
        if (gr0 < n) {
            *(float2*)(Yd + (size_t)gr0 * 128 + col) =
                make_float2(accD[nt][0] * SD, accD[nt][1] * SD);
            *(float2*)(Ye + (size_t)gr0 * 128 + col) =
                make_float2(accE[nt][0] * e0, accE[nt][1] * e0);
        }
        if (gr1 < n) {
            *(float2*)(Yd + (size_t)gr1 * 128 + col) =
                make_float2(accD[nt][2] * SD, accD[nt][3] * SD);
            *(float2*)(Ye + (size_t)gr1 * 128 + col) =
                make_float2(accE[nt][2] * e1, accE[nt][3] * e1);
        }
    }
}

// ===================== source epilogue (+residual, +X^T fp16 out) ===========
__global__ __launch_bounds__(256)
void epi_src(const float* __restrict__ Y, const float* __restrict__ W,
             const float* __restrict__ bias, const float* __restrict__ prev,
             float* __restrict__ out, u16* __restrict__ Xf, int n)
{
    __shared__ float Ws[128][64];
    __shared__ float Y1s[8][128];
    __shared__ float Y2s[8][128];
    __shared__ float oS[8][128];
    const int tid = threadIdx.x, r0 = blockIdx.x * 8;
    for (int i = tid; i < 8192; i += 256) Ws[i >> 6][i & 63] = W[i];
    const float* __restrict__ Y2 = Y + (size_t)n * 128;
    for (int i = tid; i < 1024; i += 256) {
        int r = i >> 7, c = i & 127;
        size_t gi = (size_t)(r0 + r) * 128 + c;
        Y1s[r][c] = Y[gi]; Y2s[r][c] = Y2[gi];
    }
    __syncthreads();
    const int c = tid & 127, rg = tid >> 7, d = c & 63, b64 = c & 64;
    const float bv = bias[d];
    for (int rr = rg; rr < 8; rr += 2) {
        float acc = bv;
#pragma unroll
        for (int k = 0; k < 64; k++) {
            acc = fmaf(Y1s[rr][b64 + k], Ws[k][d], acc);
            acc = fmaf(Y2s[rr][b64 + k], Ws[64 + k][d], acc);
        }
        float g = prev[(size_t)(r0 + rr) * 128 + c] + fmaxf(acc, 0.f);
        out[(size_t)(r0 + rr) * 128 + c] = g;
        oS[rr][c] = g;
    }
    __syncthreads();
    if (tid < 128) {
        float v[8];
#pragma unroll
        for (int j = 0; j < 8; j++) v[j] = oS[j][tid];
        *(uint4*)(Xf + (size_t)tid * n + r0) = pack8(v);
    }
}

// ===================== VNA epilogue (batched over 3 layers) =================
__global__ __launch_bounds__(256)
void epi_vna(const float* __restrict__ Y, const float* __restrict__ W,
             const float* __restrict__ bias, float* __restrict__ semb, int n)
{
    __shared__ float Ws[128][64];
    __shared__ float Y1s[8][128];
    __shared__ float Y2s[8][128];
    const int tid = threadIdx.x, r0 = blockIdx.x * 8, y = blockIdx.y;
    const float* __restrict__ Wp = W + y * 8192;
    const float* __restrict__ Y1 = Y + (size_t)(2 * y) * n * 128;
    const float* __restrict__ Y2 = Y1 + (size_t)n * 128;
    float* __restrict__ out = semb + (size_t)y * n * 128;
    for (int i = tid; i < 8192; i += 256) Ws[i >> 6][i & 63] = Wp[i];
    for (int i = tid; i < 1024; i += 256) {
        int r = i >> 7, c = i & 127;
        size_t gi = (size_t)(r0 + r) * 128 + c;
        Y1s[r][c] = Y1[gi]; Y2s[r][c] = Y2[gi];
    }
    __syncthreads();
    const int c = tid & 127, rg = tid >> 7, d = c & 63, b64 = c & 64;
    const float bv = bias[y * 64 + d];
    for (int rr = rg; rr < 8; rr += 2) {
        float acc = bv;
#pragma unroll
        for (int k = 0; k < 64; k++) {
            acc = fmaf(Y1s[rr][b64 + k], Ws[k][d], acc);
            acc = fmaf(Y2s[rr][b64 + k], Ws[64 + k][d], acc);
        }
        out[(size_t)(r0 + rr) * 128 + c] = fmaxf(acc, 0.f);
    }
}

// ===================== target epilogue + gated fusion (+X^T out) ============
#define SMEM_TGT 49152
__global__ __launch_bounds__(256)
void epi_tgt(const float* __restrict__ Y, const float* __restrict__ W,
             const float* __restrict__ bias, const float* __restrict__ S,
             const float* __restrict__ fWt, const float* __restrict__ fWs,
             const float* __restrict__ fb, float* __restrict__ xt,
             u16* __restrict__ Xf, int n)
{
    extern __shared__ __align__(16) char dsm[];
    float* Wbuf = (float*)dsm;
    float (*Y1s)[128] = (float(*)[128])(dsm + 32768);
    float (*Y2s)[128] = (float(*)[128])(dsm + 36864);
    float (*tS)[128]  = (float(*)[128])(dsm + 40960);
    float (*sS)[128]  = (float(*)[128])(dsm + 45056);
    const int tid = threadIdx.x, r0 = blockIdx.x * 8;
    for (int i = tid; i < 8192; i += 256) Wbuf[i] = W[i];
    const float* __restrict__ Y2 = Y + (size_t)n * 128;
    for (int i = tid; i < 1024; i += 256) {
        int r = i >> 7, c = i & 127;
        size_t gi = (size_t)(r0 + r) * 128 + c;
        Y1s[r][c] = Y[gi]; Y2s[r][c] = Y2[gi];
        sS[r][c] = S[gi];
    }
    __syncthreads();
    const int c = tid & 127, rg = tid >> 7, d = c & 63, b64 = c & 64;
    const float bv = bias[d];
    for (int rr = rg; rr < 8; rr += 2) {
        float acc = bv;
#pragma unroll
        for (int k = 0; k < 64; k++) {
            acc = fmaf(Y1s[rr][b64 + k], Wbuf[k * 64 + d], acc);
            acc = fmaf(Y2s[rr][b64 + k], Wbuf[(64 + k) * 64 + d], acc);
        }
        tS[rr][c] = fmaxf(acc, 0.f);
    }
    __syncthreads();
    for (int i = tid; i < 4096; i += 256) { Wbuf[i] = fWt[i]; Wbuf[4096 + i] = fWs[i]; }
    __syncthreads();
    const float fbv = fb[d];
    for (int rr = rg; rr < 8; rr += 2) {
        float za = fbv;
#pragma unroll
        for (int k = 0; k < 64; k++) {
            za = fmaf(tS[rr][b64 + k], Wbuf[k * 64 + d], za);
            za = fmaf(sS[rr][b64 + k], Wbuf[4096 + k * 64 + d], za);
        }
        float z = 1.f / (1.f + expf(-za));
        float tv = tS[rr][c], sv = sS[rr][c];
        size_t gi = (size_t)(r0 + rr) * 128 + c;
        float nx = xt[gi] + z * tv + (1.f - z) * sv;
        xt[gi] = nx;
        Y1s[rr][c] = nx;
    }
    __syncthreads();
    if (Xf && tid < 128) {
        float v[8];
#pragma unroll
        for (int j = 0; j < 8; j++) v[j] = Y1s[j][tid];
        *(uint4*)(Xf + (size_t)tid * n + r0) = pack8(v);
    }
}

// ===================== launcher =============================================
extern "C" void kernel_launch(void* const* d_in, const int* in_sizes, int n_in,
                              void* d_out, int out_size)
{
    (void)in_sizes; (void)n_in; (void)out_size;
    const float* A0      = (const float*)d_in[0];
    const float* A1      = (const float*)d_in[1];
    const float* A2      = (const float*)d_in[2];
    const float* x0      = (const float*)d_in[3];
    const float* x1      = (const float*)d_in[4];
    const float* src_nv1 = (const float*)d_in[5];
    const float* src_nv2 = (const float*)d_in[6];
    const float* src_W   = (const float*)d_in[7];
    const float* src_b   = (const float*)d_in[8];
    const float* vna_nv1 = (const float*)d_in[9];
    const float* vna_nv2 = (const float*)d_in[10];
    const float* vna_W   = (const float*)d_in[11];
    const float* vna_b   = (const float*)d_in[12];
    const float* tgt_nv1 = (const float*)d_in[13];
    const float* tgt_nv2 = (const float*)d_in[14];
    const float* tgt_W   = (const float*)d_in[15];
    const float* tgt_b   = (const float*)d_in[16];
    const float* fus_Wt  = (const float*)d_in[17];
    const float* fus_Ws  = (const float*)d_in[18];
    const float* fus_b   = (const float*)d_in[19];

    u16 *A0f, *A1f, *A2f, *Es, *Ev, *Et, *Xf;
    float *src_inv, *vna_inv, *tgt_inv, *lr, *semb, *Yb, *xtb;
    cudaGetSymbolAddress((void**)&A0f, g_A0f);
    cudaGetSymbolAddress((void**)&A1f, g_A1f);
    cudaGetSymbolAddress((void**)&A2f, g_A2f);
    cudaGetSymbolAddress((void**)&Es, g_Es);
    cudaGetSymbolAddress((void**)&Ev, g_Ev);
    cudaGetSymbolAddress((void**)&Et, g_Et);
    cudaGetSymbolAddress((void**)&Xf, g_Xf);
    cudaGetSymbolAddress((void**)&src_inv, g_src_inv);
    cudaGetSymbolAddress((void**)&vna_inv, g_vna_inv);
    cudaGetSymbolAddress((void**)&tgt_inv, g_tgt_inv);
    cudaGetSymbolAddress((void**)&lr, g_lr);
    cudaGetSymbolAddress((void**)&semb, g_semb);
    cudaGetSymbolAddress((void**)&Yb, g_Y);
    cudaGetSymbolAddress((void**)&xtb, g_xt);

    cudaFuncSetAttribute(hmma_gemm3m, cudaFuncAttributeMaxDynamicSharedMemorySize, SMEM_GEMM);
    cudaFuncSetAttribute(epi_tgt, cudaFuncAttributeMaxDynamicSharedMemorySize, SMEM_TGT);
    cudaFuncSetAttribute(adp_fused, cudaFuncAttributeMaxDynamicSharedMemorySize, 4 * NS * 4);

    const size_t SLOT = (size_t)128 * NS;
    u16* Xf3 = Xf + 3 * SLOT;
    const int xS = ((NS + 31) / 32) * 2;   // 314
    const int xT = ((NT + 31) / 32) * 2;   // 250

    // ---- src chain first: profiled launch idx 3 = first src GEMM ----
    pack_prep<<<NS / 8, 256>>>(x1, lr, Xf, NS);
    tofp16_kernel<<<(NS * NS / 4 + 255) / 256, 256>>>(A2, A2f, NS * NS / 4);
    adp_fused<<<NS / 4, 256, 4 * NS * 4>>>(src_nv1, src_nv2, Es, src_inv, NS);
    for (int i = 0; i < 2; i++) {
        hmma_gemm3m<<<dim3(xS, 1), 128, SMEM_GEMM>>>(A2f, Es, src_inv,
            Xf + i * SLOT, Yb, NS, NS);
        epi_src<<<NS / 8, 256>>>(Yb, src_W + i * 8192, src_b + i * 64,
            lr + (size_t)i * NS * 128, lr + (size_t)(i + 1) * NS * 128,
            Xf + (i + 1) * SLOT, NS);
    }

    // ---- rest of prep ----
    pack_prep<<<NT / 8, 256>>>(x0, xtb, Xf3, NT);
    tofp16_kernel<<<(NT * NT / 4 + 255) / 256, 256>>>(A0, A0f, NT * NT / 4);
    tofp16_kernel<<<(NT * NS / 4 + 255) / 256, 256>>>(A1, A1f, NT * NS / 4);
    adp_fused<<<NT / 4, 256, 4 * NS * 4>>>(vna_nv1, vna_nv2, Ev, vna_inv, NS);
    adp_fused<<<NT / 4, 256, 4 * NT * 4>>>(tgt_nv1, tgt_nv2, Et, tgt_inv, NT);

    // ---- VNA block: 3 layers batched ----
    hmma_gemm3m<<<dim3(xT, 3), 128, SMEM_GEMM>>>(A1f, Ev, vna_inv, Xf, Yb, NT, NS);
    epi_vna<<<dim3(NT / 8, 3), 256>>>(Yb, vna_W, vna_b, semb, NT);

    // ---- Target GC block with gated fusion ----
    for (int i = 0; i < 3; i++) {
        hmma_gemm3m<<<dim3(xT, 1), 128, SMEM_GEMM>>>(A0f, Et, tgt_inv, Xf3, Yb, NT, NT);
        epi_tgt<<<NT / 8, 256, SMEM_TGT>>>(Yb, tgt_W + i * 8192, tgt_b + i * 64,
            semb + (size_t)i * NT * 128, fus_Wt + i * 4096, fus_Ws + i * 4096,
            fus_b + i * 64, xtb, (i < 2) ? Xf3 : (u16*)nullptr, NT);
    }

    unpack_kernel<<<(NT * 128 + 255) / 256, 256>>>(xtb, (float*)d_out, NT);
}

// round 10
// speedup vs baseline: 2.1027x; 1.0069x over previous
#include <cuda_runtime.h>
#include <cuda_fp16.h>
#include <math.h>
#include <stdint.h>

#define NT 4000
#define NS 5000
#define LOG2E 1.4426950408889634f
typedef unsigned short u16;

// ===================== scratch =============================================
__device__ __align__(16) u16 g_A0f[16000000];
__device__ __align__(16) u16 g_A1f[20000000];
__device__ __align__(16) u16 g_A2f[25000000];
__device__ __align__(16) u16 g_Es[25000000];
__device__ __align__(16) u16 g_Ev[20000000];
__device__ __align__(16) u16 g_Et[16000000];
__device__ __align__(16) u16 g_Xf[2432000];
__device__ float g_src_inv[NS];
__device__ float g_vna_inv[NT];
__device__ float g_tgt_inv[NT];
__device__ __align__(16) float g_lr[3 * NS * 128];
__device__ __align__(16) float g_semb[3 * NT * 128];
__device__ __align__(16) float g_Y[6200000];   // partials: [z][slot][n*128]
__device__ __align__(16) float g_xt[NT * 128];

// ===================== PTX helpers =========================================
__device__ __forceinline__ uint32_t smem_u32(const void* p) {
    uint32_t a;
    asm("{ .reg .u64 t; cvta.to.shared.u64 t, %1; cvt.u32.u64 %0, t; }" : "=r"(a) : "l"(p));
    return a;
}
#define CP_ASYNC16(saddr, gaddr, sz) \
    asm volatile("cp.async.ca.shared.global [%0], [%1], 16, %2;" :: "r"(saddr), "l"(gaddr), "r"(sz))
#define CP_COMMIT() asm volatile("cp.async.commit_group;" ::: "memory")
#define CP_WAIT1()  asm volatile("cp.async.wait_group 1;" ::: "memory")
#define LDSM4(r, a) \
    asm volatile("ldmatrix.sync.aligned.m8n8.x4.shared.b16 {%0,%1,%2,%3}, [%4];" \
        : "=r"((r)[0]), "=r"((r)[1]), "=r"((r)[2]), "=r"((r)[3]) : "r"(a))
#define MMA_FP16(c, A, b0, b1) \
    asm volatile("mma.sync.aligned.m16n8k16.row.col.f32.f16.f16.f32 " \
        "{%0,%1,%2,%3},{%4,%5,%6,%7},{%8,%9},{%0,%1,%2,%3};" \
        : "+f"((c)[0]), "+f"((c)[1]), "+f"((c)[2]), "+f"((c)[3]) \
        : "r"((A)[0]), "r"((A)[1]), "r"((A)[2]), "r"((A)[3]), "r"(b0), "r"(b1))

__device__ __forceinline__ uint32_t pack_h2(float a, float b) {
    return (uint32_t)__half_as_ushort(__float2half_rn(a)) |
           ((uint32_t)__half_as_ushort(__float2half_rn(b)) << 16);
}
__device__ __forceinline__ uint4 pack8(const float* v) {
    uint4 H;
    H.x = pack_h2(v[0], v[1]); H.y = pack_h2(v[2], v[3]);
    H.z = pack_h2(v[4], v[5]); H.w = pack_h2(v[6], v[7]);
    return H;
}
__device__ __forceinline__ uint32_t swz(uint32_t x) { return x ^ ((x >> 3) & 0x70); }

// ===================== small kernels ========================================
__global__ void unpack_kernel(const float* __restrict__ xp, float* __restrict__ out, int n) {
    int i = blockIdx.x * blockDim.x + threadIdx.x;
    if (i >= n * 128) return;
    int r = i >> 7, c = i & 127, b = c >> 6, d = c & 63;
    out[((size_t)b * n + r) * 64 + d] = xp[i];
}
__global__ void tofp16_kernel(const float* __restrict__ A, u16* __restrict__ F, int n4) {
    int i = blockIdx.x * blockDim.x + threadIdx.x;
    if (i >= n4) return;
    float4 v = ((const float4*)A)[i];
    uint2 o;
    o.x = pack_h2(v.x * 4096.f, v.y * 4096.f);
    o.y = pack_h2(v.z * 4096.f, v.w * 4096.f);
    ((uint2*)F)[i] = o;
}
__global__ __launch_bounds__(256)
void pack_prep(const float* __restrict__ x, float* __restrict__ xp,
               u16* __restrict__ Xf, int n)
{
    __shared__ float t[8][128];
    const int tid = threadIdx.x, r0 = blockIdx.x * 8;
    for (int i = tid; i < 1024; i += 256) {
        int r = i >> 7, c = i & 127, b = c >> 6, d = c & 63;
        float v = x[((size_t)b * n + r0 + r) * 64 + d];
        xp[(size_t)(r0 + r) * 128 + c] = v;
        t[r][c] = v;
    }
    __syncthreads();
    if (tid < 128) {
        float v[8];
#pragma unroll
        for (int j = 0; j < 8; j++) v[j] = t[j][tid];
        *(uint4*)(Xf + (size_t)tid * n + r0) = pack8(v);
    }
}

// ===================== fused adaptive adjacency (4 rows/CTA, occ 2) =========
__global__ __launch_bounds__(256)
void adp_fused(const float* __restrict__ nv1, const float* __restrict__ nv2,
               u16* __restrict__ E, float* __restrict__ inv, int ncols)
{
    extern __shared__ float ds[];
    __shared__ float v1s[4][30];
    __shared__ float red[8][4];
    __shared__ float Mrow[4];
    const int tid = threadIdx.x, r0 = blockIdx.x * 4;
    const int lane = tid & 31, wrp = tid >> 5;
    if (tid < 120) v1s[tid / 30][tid % 30] = nv1[(size_t)(r0 + tid / 30) * 30 + tid % 30];
    __syncthreads();

    float mx[4];
#pragma unroll
    for (int r = 0; r < 4; r++) mx[r] = 0.f;
    for (int c = tid; c < ncols; c += 256) {
        float col[30];
#pragma unroll
        for (int q = 0; q < 30; q++) col[q] = nv2[(size_t)q * ncols + c];
#pragma unroll
        for (int r = 0; r < 4; r++) {
            float dot = 0.f;
#pragma unroll
            for (int q = 0; q < 30; q++) dot = fmaf(v1s[r][q], col[q], dot);
            float dp = fmaxf(dot, 0.f);
            ds[r * ncols + c] = dp;
            mx[r] = fmaxf(mx[r], dp);
        }
    }
#pragma unroll
    for (int r = 0; r < 4; r++) {
        float v = mx[r];
#pragma unroll
        for (int off = 16; off > 0; off >>= 1)
            v = fmaxf(v, __shfl_down_sync(0xffffffffu, v, off));
        if (lane == 0) red[wrp][r] = v;
    }
    __syncthreads();
    if (tid < 4) {
        float v = red[0][tid];
#pragma unroll
        for (int w = 1; w < 8; w++) v = fmaxf(v, red[w][tid]);
        Mrow[tid] = v;
    }
    __syncthreads();

    float M[4], ps[4];
#pragma unroll
    for (int r = 0; r < 4; r++) { M[r] = Mrow[r]; ps[r] = 0.f; }
    for (int c = tid * 2; c < ncols; c += 512) {
#pragma unroll
        for (int r = 0; r < 4; r++) {
            size_t idx = (size_t)(r0 + r) * ncols + c;
            float t0 = (ds[r * ncols + c]     - M[r]) * LOG2E;
            float t1 = (ds[r * ncols + c + 1] - M[r]) * LOG2E;
            __half2 tin = __floats2half2_rn(t0, t1);
            uint32_t ti = *(uint32_t*)&tin, eo;
            asm("ex2.approx.f16x2 %0, %1;" : "=r"(eo) : "r"(ti));
            *(uint32_t*)(E + idx) = eo;
            float2 ef = __half22float2(*(__half2*)&eo);
            ps[r] += ef.x + ef.y;
        }
    }
#pragma unroll
    for (int r = 0; r < 4; r++) {
        float v = ps[r];
#pragma unroll
        for (int off = 16; off > 0; off >>= 1) v += __shfl_down_sync(0xffffffffu, v, off);
        if (lane == 0) red[wrp][r] = v;
    }
    __syncthreads();
    if (tid < 4) {
        float s = 0.f;
#pragma unroll
        for (int w = 0; w < 8; w++) s += red[w][tid];
        inv[r0 + tid] = 1.0f / s;
    }
}

// ===================== merged-support split-K HMMA GEMM =====================
// CTA = 32 rows x 64 cols, both supports, K-split via blockIdx.z.
// Y partial layout: [(z*2*ny)+(y*2+sup)][n*128]
#define GKT 64
#define STAGE_B 16384
#define SMEM_GEMM (2 * STAGE_B)

__device__ __forceinline__ void stage_ldm(uint32_t sdst,
    const u16* __restrict__ Ad, const u16* __restrict__ Ae, const u16* __restrict__ B,
    int row0, int kbase, int n, int kend, int m, int tid)
{
#pragma unroll
    for (int t = 0; t < 2; t++) {
        int id = tid + t * 128;
        int r = id >> 3, kc = id & 7;
        int gr = row0 + r, gk = kbase + kc * 8;
        bool v = (gr < n) && (gk < kend);
        size_t gi = (size_t)(v ? gr : 0) * m + (v ? gk : 0);
        uint32_t sw = swz(r * 128 + kc * 16);
        unsigned sz = v ? 16u : 0u;
        CP_ASYNC16(sdst + sw, Ad + gi, sz);
        CP_ASYNC16(sdst + 4096 + sw, Ae + gi, sz);
    }
#pragma unroll
    for (int t = 0; t < 4; t++) {
        int id = tid + t * 128;
        int cr = id >> 3, kc = id & 7;
        int gk = kbase + kc * 8;
        bool v = (gk < kend);
        size_t gi = (size_t)cr * m + (v ? gk : 0);
        uint32_t sw = swz(cr * 128 + kc * 16);
        CP_ASYNC16(sdst + 8192 + sw, B + gi, v ? 16u : 0u);
    }
}

__global__ __launch_bounds__(128, 4)
void hmma_gemm3m(const u16* __restrict__ Af, const u16* __restrict__ Ef,
                 const float* __restrict__ invsum,
                 const u16* __restrict__ Xf,
                 float* __restrict__ Y, int n, int m, int mh, int ny)
{
    extern __shared__ __align__(128) char smem[];
    const uint32_t sb = smem_u32(smem);
    const int tid = threadIdx.x, lane = tid & 31, wid = tid >> 5;
    const int wm = wid >> 1, wn = wid & 1;
    const int tile = blockIdx.x >> 1, nh = blockIdx.x & 1;
    const int row0 = tile * 32, col0 = nh * 64;
    const int yb = blockIdx.y % ny, zs = blockIdx.y / ny;   // X slot, K-split idx
    const u16* __restrict__ B = Xf + ((size_t)yb * 128 + col0) * m;
    const int k0 = zs * mh, kend = min(m, k0 + mh);
    const int ktn = (kend - k0 + GKT - 1) / GKT;

    float accD[4][4], accE[4][4];
#pragma unroll
    for (int j = 0; j < 4; j++)
#pragma unroll
        for (int q = 0; q < 4; q++) { accD[j][q] = 0.f; accE[j][q] = 0.f; }

    uint32_t arow, axor;
    { int r = wm * 16 + (lane & 7) + (((lane >> 3) & 1) << 3);
      arow = (uint32_t)r * 128; axor = ((uint32_t)r * 16) & 0x70; }
    const uint32_t akbs = ((lane >> 4) & 1) * 16;
    uint32_t brow[2], bxor[2];
#pragma unroll
    for (int bt = 0; bt < 2; bt++) {
        int r = wn * 32 + bt * 16 + (lane & 7) + (((lane >> 4) & 1) << 3);
        brow[bt] = (uint32_t)r * 128; bxor[bt] = ((uint32_t)r * 16) & 0x70;
    }
    const uint32_t bkbs = ((lane >> 3) & 1) * 16;

    stage_ldm(sb, Af, Ef, B, row0, k0, n, kend, m, tid);
    CP_COMMIT();

    for (int kt = 0; kt < ktn; kt++) {
        if (kt + 1 < ktn)
            stage_ldm(sb + ((kt + 1) & 1) * STAGE_B, Af, Ef, B,
                      row0, k0 + (kt + 1) * GKT, n, kend, m, tid);
        CP_COMMIT();
        CP_WAIT1();
        __syncthreads();
        const uint32_t stb = sb + (kt & 1) * STAGE_B;
#pragma unroll
        for (int ks = 0; ks < 4; ks++) {
            const uint32_t kb = ks * 32;
            uint32_t fad[4], fae[4], fb[2][4];
            LDSM4(fad, stb + arow + ((kb + akbs) ^ axor));
            LDSM4(fae, stb + 4096 + arow + ((kb + akbs) ^ axor));
#pragma unroll
            for (int bt = 0; bt < 2; bt++)
                LDSM4(fb[bt], stb + 8192 + brow[bt] + ((kb + bkbs) ^ bxor[bt]));
#pragma unroll
            for (int nt = 0; nt < 4; nt++) {
                const int g = nt >> 1, h = (nt & 1) << 1;
                MMA_FP16(accD[nt], fad, fb[g][h], fb[g][h + 1]);
                MMA_FP16(accE[nt], fae, fb[g][h], fb[g][h + 1]);
            }
        }
        __syncthreads();
    }

    float* __restrict__ Yd = Y + (size_t)(zs * 2 * ny + yb * 2) * n * 128;
    float* __restrict__ Ye = Yd + (size_t)n * 128;
    const int gr0 = row0 + wm * 16 + (lane >> 2), gr1 = gr0 + 8;
    const float SD = 2.44140625e-4f;
    const float e0 = (gr0 < n) ? invsum[gr0] : 0.f;
    const float e1 = (gr1 < n) ? invsum[gr1] : 0.f;
#pragma unroll
    for (int nt = 0; nt < 4; nt++) {
        int col = col0 + wn * 32 + nt * 8 + ((lane & 3) << 1);
        if (gr0 < n) {
            *(float2*)(Yd + (size_t)gr0 * 128 + col) =
                make_float2(accD[nt][0] * SD, accD[nt][1] * SD);
            *(float2*)(Ye + (size_t)gr0 * 128 + col) =
                make_float2(accE[nt][0] * e0, accE[nt][1] * e0);
        }
        if (gr1 < n) {
            *(float2*)(Yd + (size_t)gr1 * 128 + col) =
                make_float2(accD[nt][2] * SD, accD[nt][3] * SD);
            *(float2*)(Ye + (size_t)gr1 * 128 + col) =
                make_float2(accE[nt][2] * e1, accE[nt][3] * e1);
        }
    }
}

// ===================== source epilogue (+residual, +X^T fp16 out) ===========
__global__ __launch_bounds__(256)
void epi_src(const float* __restrict__ Y, const float* __restrict__ W,
             const float* __restrict__ bias, const float* __restrict__ prev,
             float* __restrict__ out, u16* __restrict__ Xf, int n, size_t ps)
{
    __shared__ float Ws[128][64];
    __shared__ float Y1s[8][128];
    __shared__ float Y2s[8][128];
    __shared__ float oS[8][128];
    const int tid = threadIdx.x, r0 = blockIdx.x * 8;
    for (int i = tid; i < 8192; i += 256) Ws[i >> 6][i & 63] = W[i];
    const float* __restrict__ Y2 = Y + (size_t)n * 128;
    for (int i = tid; i < 1024; i += 256) {
        int r = i >> 7, c = i & 127;
        size_t gi = (size_t)(r0 + r) * 128 + c;
        Y1s[r][c] = Y[gi] + Y[gi + ps];
        Y2s[r][c] = Y2[gi] + Y2[gi + ps];
    }
    __syncthreads();
    const int c = tid & 127, rg = tid >> 7, d = c & 63, b64 = c & 64;
    const float bv = bias[d];
    for (int rr = rg; rr < 8; rr += 2) {
        float acc = bv;
#pragma unroll
        for (int k = 0; k < 64; k++) {
            acc = fmaf(Y1s[rr][b64 + k], Ws[k][d], acc);
            acc = fmaf(Y2s[rr][b64 + k], Ws[64 + k][d], acc);
        }
        float g = prev[(size_t)(r0 + rr) * 128 + c] + fmaxf(acc, 0.f);
        out[(size_t)(r0 + rr) * 128 + c] = g;
        oS[rr][c] = g;
    }
    __syncthreads();
    if (tid < 128) {
        float v[8];
#pragma unroll
        for (int j = 0; j < 8; j++) v[j] = oS[j][tid];
        *(uint4*)(Xf + (size_t)tid * n + r0) = pack8(v);
    }
}

// ===================== VNA epilogue (batched over 3 layers) =================
__global__ __launch_bounds__(256)
void epi_vna(const float* __restrict__ Y, const float* __restrict__ W,
             const float* __restrict__ bias, float* __restrict__ semb, int n, size_t ps)
{
    __shared__ float Ws[128][64];
    __shared__ float Y1s[8][128];
    __shared__ float Y2s[8][128];
    const int tid = threadIdx.x, r0 = blockIdx.x * 8, y = blockIdx.y;
    const float* __restrict__ Wp = W + y * 8192;
    const float* __restrict__ Y1 = Y + (size_t)(2 * y) * n * 128;
    const float* __restrict__ Y2 = Y1 + (size_t)n * 128;
    float* __restrict__ out = semb + (size_t)y * n * 128;
    for (int i = tid; i < 8192; i += 256) Ws[i >> 6][i & 63] = Wp[i];
    for (int i = tid; i < 1024; i += 256) {
        int r = i >> 7, c = i & 127;
        size_t gi = (size_t)(r0 + r) * 128 + c;
        Y1s[r][c] = Y1[gi] + Y1[gi + ps];
        Y2s[r][c] = Y2[gi] + Y2[gi + ps];
    }
    __syncthreads();
    const int c = tid & 127, rg = tid >> 7, d = c & 63, b64 = c & 64;
    const float bv = bias[y * 64 + d];
    for (int rr = rg; rr < 8; rr += 2) {
        float acc = bv;
#pragma unroll
        for (int k = 0; k < 64; k++) {
            acc = fmaf(Y1s[rr][b64 + k], Ws[k][d], acc);
            acc = fmaf(Y2s[rr][b64 + k], Ws[64 + k][d], acc);
        }
        out[(size_t)(r0 + rr) * 128 + c] = fmaxf(acc, 0.f);
    }
}

// ===================== target epilogue + gated fusion (+X^T out) ============
#define SMEM_TGT 49152
__global__ __launch_bounds__(256)
void epi_tgt(const float* __restrict__ Y, const float* __restrict__ W,
             const float* __restrict__ bias, const float* __restrict__ S,
             const float* __restrict__ fWt, const float* __restrict__ fWs,
             const float* __restrict__ fb, float* __restrict__ xt,
             u16* __restrict__ Xf, int n, size_t ps)
{
    extern __shared__ __align__(16) char dsm[];
    float* Wbuf = (float*)dsm;
    float (*Y1s)[128] = (float(*)[128])(dsm + 32768);
    float (*Y2s)[128] = (float(*)[128])(dsm + 36864);
    float (*tS)[128]  = (float(*)[128])(dsm + 40960);
    float (*sS)[128]  = (float(*)[128])(dsm + 45056);
    const int tid = threadIdx.x, r0 = blockIdx.x * 8;
    for (int i = tid; i < 8192; i += 256) Wbuf[i] = W[i];
    const float* __restrict__ Y2 = Y + (size_t)n * 128;
    for (int i = tid; i < 1024; i += 256) {
        int r = i >> 7, c = i & 127;
        size_t gi = (size_t)(r0 + r) * 128 + c;
        Y1s[r][c] = Y[gi] + Y[gi + ps];
        Y2s[r][c] = Y2[gi] + Y2[gi + ps];
        sS[r][c] = S[gi];
    }
    __syncthreads();
    const int c = tid & 127, rg = tid >> 7, d = c & 63, b64 = c & 64;
    const float bv = bias[d];
    for (int rr = rg; rr < 8; rr += 2) {
        float acc = bv;
#pragma unroll
        for (int k = 0; k < 64; k++) {
            acc = fmaf(Y1s[rr][b64 + k], Wbuf[k * 64 + d], acc);
            acc = fmaf(Y2s[rr][b64 + k], Wbuf[(64 + k) * 64 + d], acc);
        }
        tS[rr][c] = fmaxf(acc, 0.f);
    }
    __syncthreads();
    for (int i = tid; i < 4096; i += 256) { Wbuf[i] = fWt[i]; Wbuf[4096 + i] = fWs[i]; }
    __syncthreads();
    const float fbv = fb[d];
    for (int rr = rg; rr < 8; rr += 2) {
        float za = fbv;
#pragma unroll
        for (int k = 0; k < 64; k++) {
            za = fmaf(tS[rr][b64 + k], Wbuf[k * 64 + d], za);
            za = fmaf(sS[rr][b64 + k], Wbuf[4096 + k * 64 + d], za);
        }
        float z = 1.f / (1.f + expf(-za));
        float tv = tS[rr][c], sv = sS[rr][c];
        size_t gi = (size_t)(r0 + rr) * 128 + c;
        float nx = xt[gi] + z * tv + (1.f - z) * sv;
        xt[gi] = nx;
        Y1s[rr][c] = nx;
    }
    __syncthreads();
    if (Xf && tid < 128) {
        float v[8];
#pragma unroll
        for (int j = 0; j < 8; j++) v[j] = Y1s[j][tid];
        *(uint4*)(Xf + (size_t)tid * n + r0) = pack8(v);
    }
}

// ===================== launcher =============================================
extern "C" void kernel_launch(void* const* d_in, const int* in_sizes, int n_in,
                              void* d_out, int out_size)
{
    (void)in_sizes; (void)n_in; (void)out_size;
    const float* A0      = (const float*)d_in[0];
    const float* A1      = (const float*)d_in[1];
    const float* A2      = (const float*)d_in[2];
    const float* x0      = (const float*)d_in[3];
    const float* x1      = (const float*)d_in[4];
    const float* src_nv1 = (const float*)d_in[5];
    const float* src_nv2 = (const float*)d_in[6];
    const float* src_W   = (const float*)d_in[7];
    const float* src_b   = (const float*)d_in[8];
    const float* vna_nv1 = (const float*)d_in[9];
    const float* vna_nv2 = (const float*)d_in[10];
    const float* vna_W   = (const float*)d_in[11];
    const float* vna_b   = (const float*)d_in[12];
    const float* tgt_nv1 = (const float*)d_in[13];
    const float* tgt_nv2 = (const float*)d_in[14];
    const float* tgt_W   = (const float*)d_in[15];
    const float* tgt_b   = (const float*)d_in[16];
    const float* fus_Wt  = (const float*)d_in[17];
    const float* fus_Ws  = (const float*)d_in[18];
    const float* fus_b   = (const float*)d_in[19];

    u16 *A0f, *A1f, *A2f, *Es, *Ev, *Et, *Xf;
    float *src_inv, *vna_inv, *tgt_inv, *lr, *semb, *Yb, *xtb;
    cudaGetSymbolAddress((void**)&A0f, g_A0f);
    cudaGetSymbolAddress((void**)&A1f, g_A1f);
    cudaGetSymbolAddress((void**)&A2f, g_A2f);
    cudaGetSymbolAddress((void**)&Es, g_Es);
    cudaGetSymbolAddress((void**)&Ev, g_Ev);
    cudaGetSymbolAddress((void**)&Et, g_Et);
    cudaGetSymbolAddress((void**)&Xf, g_Xf);
    cudaGetSymbolAddress((void**)&src_inv, g_src_inv);
    cudaGetSymbolAddress((void**)&vna_inv, g_vna_inv);
    cudaGetSymbolAddress((void**)&tgt_inv, g_tgt_inv);
    cudaGetSymbolAddress((void**)&lr, g_lr);
    cudaGetSymbolAddress((void**)&semb, g_semb);
    cudaGetSymbolAddress((void**)&Yb, g_Y);
    cudaGetSymbolAddress((void**)&xtb, g_xt);

    cudaFuncSetAttribute(hmma_gemm3m, cudaFuncAttributeMaxDynamicSharedMemorySize, SMEM_GEMM);
    cudaFuncSetAttribute(epi_tgt, cudaFuncAttributeMaxDynamicSharedMemorySize, SMEM_TGT);
    cudaFuncSetAttribute(adp_fused, cudaFuncAttributeMaxDynamicSharedMemorySize, 4 * NS * 4);

    const size_t SLOT = (size_t)128 * NS;
    u16* Xf3 = Xf + 3 * SLOT;
    const int xS = ((NS + 31) / 32) * 2;   // 314
    const int xT = ((NT + 31) / 32) * 2;   // 250
    const int mhS = 2560, mhT = 2048;      // K-split halves (mult of 64)
    const size_t psS = (size_t)2 * NS * 128;   // partial stride, ny=1
    const size_t psT1 = (size_t)2 * NT * 128;  // ny=1 (tgt)
    const size_t psT3 = (size_t)6 * NT * 128;  // ny=3 (vna)

    // ---- src chain first (profiled launch idx 3 = first src GEMM) ----
    pack_prep<<<NS / 8, 256>>>(x1, lr, Xf, NS);
    tofp16_kernel<<<(NS * NS / 4 + 255) / 256, 256>>>(A2, A2f, NS * NS / 4);
    adp_fused<<<NS / 4, 256, 4 * NS * 4>>>(src_nv1, src_nv2, Es, src_inv, NS);
    for (int i = 0; i < 2; i++) {
        hmma_gemm3m<<<dim3(xS, 2), 128, SMEM_GEMM>>>(A2f, Es, src_inv,
            Xf + i * SLOT, Yb, NS, NS, mhS, 1);
        epi_src<<<NS / 8, 256>>>(Yb, src_W + i * 8192, src_b + i * 64,
            lr + (size_t)i * NS * 128, lr + (size_t)(i + 1) * NS * 128,
            Xf + (i + 1) * SLOT, NS, psS);
    }

    // ---- rest of prep ----
    pack_prep<<<NT / 8, 256>>>(x0, xtb, Xf3, NT);
    tofp16_kernel<<<(NT * NT / 4 + 255) / 256, 256>>>(A0, A0f, NT * NT / 4);
    tofp16_kernel<<<(NT * NS / 4 + 255) / 256, 256>>>(A1, A1f, NT * NS / 4);
    adp_fused<<<NT / 4, 256, 4 * NS * 4>>>(vna_nv1, vna_nv2, Ev, vna_inv, NS);
    adp_fused<<<NT / 4, 256, 4 * NT * 4>>>(tgt_nv1, tgt_nv2, Et, tgt_inv, NT);

    // ---- VNA block: 3 layers batched, K-split 2 ----
    hmma_gemm3m<<<dim3(xT, 6), 128, SMEM_GEMM>>>(A1f, Ev, vna_inv, Xf, Yb, NT, NS, mhS, 3);
    epi_vna<<<dim3(NT / 8, 3), 256>>>(Yb, vna_W, vna_b, semb, NT, psT3);

    // ---- Target GC block with gated fusion ----
    for (int i = 0; i < 3; i++) {
        hmma_gemm3m<<<dim3(xT, 2), 128, SMEM_GEMM>>>(A0f, Et, tgt_inv, Xf3, Yb, NT, NT, mhT, 1);
        epi_tgt<<<NT / 8, 256, SMEM_TGT>>>(Yb, tgt_W + i * 8192, tgt_b + i * 64,
            semb + (size_t)i * NT * 128, fus_Wt + i * 4096, fus_Ws + i * 4096,
            fus_b + i * 64, xtb, (i < 2) ? Xf3 : (u16*)nullptr, NT, psT1);
    }

    unpack_kernel<<<(NT * 128 + 255) / 256, 256>>>(xtb, (float*)d_out, NT);
}